// round 2
// baseline (speedup 1.0000x reference)
#include <cuda_runtime.h>
#include <cstdint>
#include <cstddef>

#define NNODES 50000
#define SEQ    16
#define FIN    64
#define HID    128
#define G3     384
#define NHEAD  4
#define ECONST 1600000
#define ETOT   (ECONST + NNODES)

// ---------------- scratch (device globals; no runtime allocation) -------------
__device__ float g_x0 [(size_t)NNODES * HID];
__device__ float g_x1 [(size_t)NNODES * HID];
__device__ float g_h1 [(size_t)NNODES * HID];
__device__ float g_acc[(size_t)NNODES * HID];
__device__ float g_as [NNODES * NHEAD];
__device__ float g_ad [NNODES * NHEAD];
__device__ float g_m  [NNODES * NHEAD];
__device__ float g_den[NNODES * NHEAD];
__device__ float g_e  [(size_t)ETOT * NHEAD];
__device__ int   g_ei [2 * ECONST];
__device__ int   g_flag[1];

// ---------------- helpers ----------------
__device__ __forceinline__ float f4c(const float4 v, int i) {
    switch (i & 3) { case 0: return v.x; case 1: return v.y; case 2: return v.z; default: return v.w; }
}
__device__ __forceinline__ float sigmf(float x) { return 1.f / (1.f + __expf(-x)); }
__device__ __forceinline__ float tanhfast(float x) { return 2.f / (1.f + __expf(-2.f * x)) - 1.f; }
__device__ __forceinline__ float lrelu(float x) { return x >= 0.f ? x : 0.2f * x; }
__device__ __forceinline__ void atomicMaxF(float* a, float v) {
    if (v >= 0.f) atomicMax((int*)a, __float_as_int(v));
    else          atomicMin((unsigned int*)a, __float_as_uint(v));
}
__device__ __forceinline__ void redAdd4(float* a, float4 v) {
    asm volatile("red.global.add.v4.f32 [%0], {%1,%2,%3,%4};"
                 :: "l"(a), "f"(v.x), "f"(v.y), "f"(v.z), "f"(v.w) : "memory");
}

// ---------------- edge dtype detect + convert ----------------
__global__ void detect_kernel(const void* p) {
    if (threadIdx.x == 0) {
        const int* q = (const int*)p;
        int all0 = 1;
        for (int i = 1; i < 64; i += 2) if (q[i] != 0) all0 = 0;
        g_flag[0] = all0;  // 1 => int64 source
    }
}
__global__ void convert_kernel(const void* p, int tot) {
    int is64 = g_flag[0];
    for (int i = blockIdx.x * blockDim.x + threadIdx.x; i < tot; i += gridDim.x * blockDim.x)
        g_ei[i] = is64 ? (int)((const long long*)p)[i] : ((const int*)p)[i];
}

// ---------------- GRU: fused, 32 nodes/block, 16 steps in-kernel --------------
#define GRU_LDA 36
#define GRU_SMEM ((G3 * HID + 192 * GRU_LDA) * 4)

__global__ void __launch_bounds__(256, 1) gru_kernel(
    const float* __restrict__ X, const float* __restrict__ Wih,
    const float* __restrict__ bih, const float* __restrict__ bhh,
    const float* __restrict__ Whh, float* __restrict__ outh)
{
    extern __shared__ float sm[];
    float* Wsh = sm;              // W_hh [384][128]
    float* aT  = sm + G3 * HID;   // [192][36]: rows 0..63 x_t^T, 64..191 h^T
    const int tid = threadIdx.x;
    const int node0 = blockIdx.x * 32;

    for (int i = tid; i < G3 * HID / 4; i += 256)
        ((float4*)Wsh)[i] = ((const float4*)Whh)[i];
    for (int i = tid; i < 192 * GRU_LDA; i += 256) aT[i] = 0.f;
    __syncthreads();

    const int ng = tid & 7, kg = tid >> 3;
    const int n0 = 4 * ng;

    float br_b[4], bz_b[4], bn_i[4], bn_h[4];
#pragma unroll
    for (int jj = 0; jj < 4; jj++) {
        int p = 4 * kg + jj;
        br_b[jj] = __ldg(&bih[p])       + __ldg(&bhh[p]);
        bz_b[jj] = __ldg(&bih[HID + p]) + __ldg(&bhh[HID + p]);
        bn_i[jj] = __ldg(&bih[2 * HID + p]);
        bn_h[jj] = __ldg(&bhh[2 * HID + p]);
    }

    for (int t = 0; t < SEQ; t++) {
#pragma unroll
        for (int it = 0; it < 8; it++) {
            int idx = tid + it * 256;
            int f = idx & 63, nl = idx >> 6;
            int node = node0 + nl;
            aT[f * GRU_LDA + nl] = (node < NNODES)
                ? X[(size_t)node * (SEQ * FIN) + t * FIN + f] : 0.f;
        }
        __syncthreads();

        float ar[16], az[16], ani[16], anh[16];
#pragma unroll
        for (int q = 0; q < 16; q++) { ar[q] = az[q] = ani[q] = anh[q] = 0.f; }

#pragma unroll 1
        for (int k = 0; k < FIN; k += 4) {            // x half (W_ih from L2)
            float4 av[4];
#pragma unroll
            for (int kk = 0; kk < 4; kk++) av[kk] = *(const float4*)&aT[(k + kk) * GRU_LDA + n0];
#pragma unroll
            for (int jj = 0; jj < 4; jj++) {
                int p = 4 * kg + jj;
                float4 wr = __ldg((const float4*)&Wih[(size_t)p * FIN + k]);
                float4 wz = __ldg((const float4*)&Wih[(size_t)(HID + p) * FIN + k]);
                float4 wn = __ldg((const float4*)&Wih[(size_t)(2 * HID + p) * FIN + k]);
#pragma unroll
                for (int kk = 0; kk < 4; kk++) {
                    float a0 = f4c(wr, kk), a1 = f4c(wz, kk), a2 = f4c(wn, kk);
#pragma unroll
                    for (int i2 = 0; i2 < 4; i2++) {
                        float a = f4c(av[kk], i2);
                        ar [jj * 4 + i2] = fmaf(a, a0, ar [jj * 4 + i2]);
                        az [jj * 4 + i2] = fmaf(a, a1, az [jj * 4 + i2]);
                        ani[jj * 4 + i2] = fmaf(a, a2, ani[jj * 4 + i2]);
                    }
                }
            }
        }
#pragma unroll 1
        for (int k = 0; k < HID; k += 4) {            // h half (W_hh from smem)
            float4 av[4];
#pragma unroll
            for (int kk = 0; kk < 4; kk++) av[kk] = *(const float4*)&aT[(64 + k + kk) * GRU_LDA + n0];
#pragma unroll
            for (int jj = 0; jj < 4; jj++) {
                int p = 4 * kg + jj;
                float4 wr = *(const float4*)&Wsh[(size_t)p * HID + k];
                float4 wz = *(const float4*)&Wsh[(size_t)(HID + p) * HID + k];
                float4 wn = *(const float4*)&Wsh[(size_t)(2 * HID + p) * HID + k];
#pragma unroll
                for (int kk = 0; kk < 4; kk++) {
                    float a0 = f4c(wr, kk), a1 = f4c(wz, kk), a2 = f4c(wn, kk);
#pragma unroll
                    for (int i2 = 0; i2 < 4; i2++) {
                        float a = f4c(av[kk], i2);
                        ar [jj * 4 + i2] = fmaf(a, a0, ar [jj * 4 + i2]);
                        az [jj * 4 + i2] = fmaf(a, a1, az [jj * 4 + i2]);
                        anh[jj * 4 + i2] = fmaf(a, a2, anh[jj * 4 + i2]);
                    }
                }
            }
        }

        float hnew[16];
#pragma unroll
        for (int jj = 0; jj < 4; jj++) {
            int p = 4 * kg + jj;
#pragma unroll
            for (int i2 = 0; i2 < 4; i2++) {
                int q = jj * 4 + i2;
                float r  = sigmf(ar[q] + br_b[jj]);
                float z  = sigmf(az[q] + bz_b[jj]);
                float nn = tanhfast(ani[q] + bn_i[jj] + r * (anh[q] + bn_h[jj]));
                float hold = aT[(64 + p) * GRU_LDA + n0 + i2];
                hnew[q] = (1.f - z) * nn + z * hold;
            }
        }
        __syncthreads();
#pragma unroll
        for (int jj = 0; jj < 4; jj++) {
            int p = 4 * kg + jj;
#pragma unroll
            for (int i2 = 0; i2 < 4; i2++)
                aT[(64 + p) * GRU_LDA + n0 + i2] = hnew[jj * 4 + i2];
        }
        __syncthreads();
    }

#pragma unroll
    for (int it = 0; it < 16; it++) {
        int idx = tid + it * 256;
        int k = idx & 127, nl = idx >> 7;
        int node = node0 + nl;
        if (node < NNODES) outh[(size_t)node * HID + k] = aT[(64 + k) * GRU_LDA + nl];
    }
}

// ---------------- GAT GEMM: h = x @ W^T, 32 nodes/block ----------------
#define GEMM_SMEM ((HID * HID + HID * GRU_LDA) * 4)

__global__ void __launch_bounds__(256) gemm128_kernel(
    const float* __restrict__ Xin, const float* __restrict__ W, float* __restrict__ Hout)
{
    extern __shared__ float sm[];
    float* Wsh = sm;
    float* xT  = sm + HID * HID;
    const int tid = threadIdx.x;
    const int node0 = blockIdx.x * 32;

    for (int i = tid; i < HID * HID / 4; i += 256)
        ((float4*)Wsh)[i] = ((const float4*)W)[i];
#pragma unroll
    for (int it = 0; it < 16; it++) {
        int idx = tid + it * 256;
        int k = idx & 127, nl = idx >> 7;
        int node = node0 + nl;
        xT[k * GRU_LDA + nl] = (node < NNODES) ? Xin[(size_t)node * HID + k] : 0.f;
    }
    __syncthreads();

    const int ng = tid & 7, og = tid >> 3;
    const int n0 = 4 * ng, o0 = 4 * og;
    float acc[16];
#pragma unroll
    for (int q = 0; q < 16; q++) acc[q] = 0.f;

#pragma unroll 1
    for (int k = 0; k < HID; k += 4) {
        float4 av[4], wv[4];
#pragma unroll
        for (int kk = 0; kk < 4; kk++) av[kk] = *(const float4*)&xT[(k + kk) * GRU_LDA + n0];
#pragma unroll
        for (int jj = 0; jj < 4; jj++) wv[jj] = *(const float4*)&Wsh[(size_t)(o0 + jj) * HID + k];
#pragma unroll
        for (int jj = 0; jj < 4; jj++)
#pragma unroll
            for (int kk = 0; kk < 4; kk++) {
                float w = f4c(wv[jj], kk);
#pragma unroll
                for (int i2 = 0; i2 < 4; i2++)
                    acc[jj * 4 + i2] = fmaf(f4c(av[kk], i2), w, acc[jj * 4 + i2]);
            }
    }
#pragma unroll
    for (int i2 = 0; i2 < 4; i2++) {
        int node = node0 + n0 + i2;
        if (node < NNODES)
            *(float4*)&Hout[(size_t)node * HID + o0] =
                make_float4(acc[i2], acc[4 + i2], acc[8 + i2], acc[12 + i2]);
    }
}

// ---------------- attention prep + edge passes ----------------
__global__ void att_kernel(const float* __restrict__ h1, const float* __restrict__ asrc,
                           const float* __restrict__ adst, int n)
{
    int g = blockIdx.x * blockDim.x + threadIdx.x;
    if (g >= n * NHEAD) return;
    int node = g >> 2, hh = g & 3;
    const float* hp = h1 + (size_t)node * HID + hh * 32;
    float s = 0.f, d = 0.f;
#pragma unroll
    for (int c = 0; c < 32; c += 4) {
        float4 hv = *(const float4*)&hp[c];
        float4 sv = __ldg((const float4*)&asrc[hh * 32 + c]);
        float4 dv = __ldg((const float4*)&adst[hh * 32 + c]);
        s += hv.x * sv.x + hv.y * sv.y + hv.z * sv.z + hv.w * sv.w;
        d += hv.x * dv.x + hv.y * dv.y + hv.z * dv.z + hv.w * dv.w;
    }
    g_as[g] = s; g_ad[g] = d;
    g_m[g] = __int_as_float(0xff800000u);
    g_den[g] = 0.f;
}

__global__ void zero_kernel(float* p, int n) {
    int i = blockIdx.x * blockDim.x + threadIdx.x;
    if (i < n) p[i] = 0.f;
}

__global__ void edge_max_kernel(int E, int n) {
    int tot = E + n;
    for (int i = blockIdx.x * blockDim.x + threadIdx.x; i < tot; i += gridDim.x * blockDim.x) {
        int s, d;
        if (i < E) { s = g_ei[i]; d = g_ei[E + i]; } else { s = d = i - E; }
        float4 a = *(const float4*)&g_as[s * 4];
        float4 b = *(const float4*)&g_ad[d * 4];
        float4 ev = make_float4(lrelu(a.x + b.x), lrelu(a.y + b.y),
                                lrelu(a.z + b.z), lrelu(a.w + b.w));
        *(float4*)&g_e[(size_t)i * 4] = ev;
        atomicMaxF(&g_m[d * 4 + 0], ev.x);
        atomicMaxF(&g_m[d * 4 + 1], ev.y);
        atomicMaxF(&g_m[d * 4 + 2], ev.z);
        atomicMaxF(&g_m[d * 4 + 3], ev.w);
    }
}

__global__ void edge_expsum_kernel(int E, int n) {
    int tot = E + n;
    for (int i = blockIdx.x * blockDim.x + threadIdx.x; i < tot; i += gridDim.x * blockDim.x) {
        int d = (i < E) ? g_ei[E + i] : (i - E);
        float4 ev = *(const float4*)&g_e[(size_t)i * 4];
        float4 mm = *(const float4*)&g_m[d * 4];
        float4 ex = make_float4(__expf(ev.x - mm.x), __expf(ev.y - mm.y),
                                __expf(ev.z - mm.z), __expf(ev.w - mm.w));
        *(float4*)&g_e[(size_t)i * 4] = ex;
        redAdd4(&g_den[d * 4], ex);
    }
}

__global__ void rden_kernel(int n4) {
    int i = blockIdx.x * blockDim.x + threadIdx.x;
    if (i < n4) g_den[i] = 1.f / (g_den[i] + 1e-16f);
}

__global__ void edge_scatter_kernel(const float* __restrict__ h1, float* __restrict__ out,
                                    int E, int n)
{
    int lane = threadIdx.x & 31;
    int w = (blockIdx.x * blockDim.x + threadIdx.x) >> 5;
    int nwarp = (gridDim.x * blockDim.x) >> 5;
    int tot = E + n;
    for (int i = w; i < tot; i += nwarp) {
        int s, d;
        if (i < E) { s = g_ei[i]; d = g_ei[E + i]; } else { s = d = i - E; }
        float4 ex = *(const float4*)&g_e[(size_t)i * 4];
        float4 rd = *(const float4*)&g_den[d * 4];
        float alpha = f4c(make_float4(ex.x * rd.x, ex.y * rd.y, ex.z * rd.z, ex.w * rd.w),
                          lane >> 3);
        float4 hv = *(const float4*)&h1[(size_t)s * HID + lane * 4];
        redAdd4(&out[(size_t)d * HID + lane * 4],
                make_float4(hv.x * alpha, hv.y * alpha, hv.z * alpha, hv.w * alpha));
    }
}

__global__ void finish_kernel(const float* __restrict__ acc, const float* __restrict__ b,
                              float* __restrict__ xout, int tot)
{
    int i = blockIdx.x * blockDim.x + threadIdx.x;
    if (i < tot) {
        float v = acc[i] + __ldg(&b[i & 127]);
        xout[i] = v > 0.f ? v : expm1f(v);
    }
}

__global__ void clf_kernel(const float* __restrict__ x, const float* __restrict__ wgt,
                           const float* __restrict__ b, float* __restrict__ out, int n)
{
    int lane = threadIdx.x & 31;
    int w = (blockIdx.x * blockDim.x + threadIdx.x) >> 5;
    if (w >= n) return;
    float4 xv = *(const float4*)&x[(size_t)w * HID + lane * 4];
    float4 wv = __ldg((const float4*)&wgt[lane * 4]);
    float s = xv.x * wv.x + xv.y * wv.y + xv.z * wv.z + xv.w * wv.w;
#pragma unroll
    for (int o = 16; o; o >>= 1) s += __shfl_xor_sync(0xffffffffu, s, o);
    if (lane == 0) out[w] = 1.f / (1.f + expf(-(s + __ldg(b))));
}

// ---------------- host side ----------------
static void run_gat(const float* xin, const float* w, const float* asrc, const float* adst,
                    const float* b, float* xout, float* h1, float* accb, int E, int n)
{
    gemm128_kernel<<<(n + 31) / 32, 256, GEMM_SMEM>>>(xin, w, h1);
    att_kernel<<<(n * NHEAD + 255) / 256, 256>>>(h1, asrc, adst, n);
    zero_kernel<<<(n * HID + 255) / 256, 256>>>(accb, n * HID);
    edge_max_kernel<<<2048, 256>>>(E, n);
    edge_expsum_kernel<<<2048, 256>>>(E, n);
    rden_kernel<<<(n * NHEAD + 255) / 256, 256>>>(n * NHEAD);
    edge_scatter_kernel<<<8192, 256>>>(h1, accb, E, n);
    finish_kernel<<<(n * HID + 255) / 256, 256>>>(accb, b, xout, n * HID);
}

extern "C" void kernel_launch(void* const* d_in, const int* in_sizes, int n_in,
                              void* d_out, int out_size)
{
    (void)in_sizes; (void)n_in; (void)out_size;
    const float* X    = (const float*)d_in[0];
    const void*  EIp  = d_in[1];
    const float* Wih  = (const float*)d_in[2];
    const float* Whh  = (const float*)d_in[3];
    const float* bih  = (const float*)d_in[4];
    const float* bhh  = (const float*)d_in[5];
    const float* g1w  = (const float*)d_in[6];
    const float* g1as = (const float*)d_in[7];
    const float* g1ad = (const float*)d_in[8];
    const float* g1b  = (const float*)d_in[9];
    const float* g2w  = (const float*)d_in[10];
    const float* g2as = (const float*)d_in[11];
    const float* g2ad = (const float*)d_in[12];
    const float* g2b  = (const float*)d_in[13];
    const float* cw   = (const float*)d_in[14];
    const float* cb   = (const float*)d_in[15];
    float* out = (float*)d_out;

    cudaFuncSetAttribute(gru_kernel, cudaFuncAttributeMaxDynamicSharedMemorySize, GRU_SMEM);
    cudaFuncSetAttribute(gemm128_kernel, cudaFuncAttributeMaxDynamicSharedMemorySize, GEMM_SMEM);

    float *x0, *x1, *h1, *acc;
    cudaGetSymbolAddress((void**)&x0,  g_x0);
    cudaGetSymbolAddress((void**)&x1,  g_x1);
    cudaGetSymbolAddress((void**)&h1,  g_h1);
    cudaGetSymbolAddress((void**)&acc, g_acc);

    detect_kernel<<<1, 32>>>(EIp);
    convert_kernel<<<2048, 256>>>(EIp, 2 * ECONST);

    gru_kernel<<<(NNODES + 31) / 32, 256, GRU_SMEM>>>(X, Wih, bih, bhh, Whh, x0);

    run_gat(x0, g1w, g1as, g1ad, g1b, x1, h1, acc, ECONST, NNODES);
    run_gat(x1, g2w, g2as, g2ad, g2b, x0, h1, acc, ECONST, NNODES);

    clf_kernel<<<(NNODES * 32 + 255) / 256, 256>>>(x0, cw, cb, out, NNODES);
}

// round 3
// speedup vs baseline: 1.0131x; 1.0131x over previous
#include <cuda_runtime.h>
#include <cstdint>
#include <cstddef>

#define NNODES 50000
#define SEQ    16
#define FIN    64
#define HID    128
#define G3     384
#define NHEAD  4
#define ECONST 1600000
#define ETOT   (ECONST + NNODES)

typedef unsigned long long u64;

// ---------------- scratch (device globals; no runtime allocation) -------------
__device__ float g_x0 [(size_t)NNODES * HID];
__device__ float g_x1 [(size_t)NNODES * HID];
__device__ float g_h1 [(size_t)NNODES * HID];
__device__ float g_acc[(size_t)NNODES * HID];
__device__ float g_as [NNODES * NHEAD];
__device__ float g_ad [NNODES * NHEAD];
__device__ float g_m  [NNODES * NHEAD];
__device__ float g_den[NNODES * NHEAD];
__device__ float g_e  [(size_t)ETOT * NHEAD];
__device__ int   g_ei [2 * ECONST];
__device__ int   g_flag[1];

// ---------------- helpers ----------------
__device__ __forceinline__ float f4c(const float4 v, int i) {
    switch (i & 3) { case 0: return v.x; case 1: return v.y; case 2: return v.z; default: return v.w; }
}
__device__ __forceinline__ float sigmf(float x) { return 1.f / (1.f + __expf(-x)); }
__device__ __forceinline__ float tanhfast(float x) { return 2.f / (1.f + __expf(-2.f * x)) - 1.f; }
__device__ __forceinline__ float lrelu(float x) { return x >= 0.f ? x : 0.2f * x; }
__device__ __forceinline__ void atomicMaxF(float* a, float v) {
    if (v >= 0.f) atomicMax((int*)a, __float_as_int(v));
    else          atomicMin((unsigned int*)a, __float_as_uint(v));
}
__device__ __forceinline__ void redAdd4(float* a, float4 v) {
    asm volatile("red.global.add.v4.f32 [%0], {%1,%2,%3,%4};"
                 :: "l"(a), "f"(v.x), "f"(v.y), "f"(v.z), "f"(v.w) : "memory");
}

// ---- packed f32x2 (SASS FFMA2; only reachable via PTX fma.rn.f32x2) ----
__device__ __forceinline__ u64 dup2(float v) {
    u64 r; asm("mov.b64 %0, {%1,%1};" : "=l"(r) : "f"(v)); return r;
}
__device__ __forceinline__ void fma2(u64& acc, u64 a, u64 b) {
    asm("fma.rn.f32x2 %0, %1, %2, %0;" : "+l"(acc) : "l"(a), "l"(b));
}
__device__ __forceinline__ float2 unpk(u64 v) {
    float2 r; asm("mov.b64 {%0,%1}, %2;" : "=f"(r.x), "=f"(r.y) : "l"(v)); return r;
}

// ---------------- edge dtype detect + convert ----------------
__global__ void detect_kernel(const void* p) {
    if (threadIdx.x == 0) {
        const int* q = (const int*)p;
        int all0 = 1;
        for (int i = 1; i < 64; i += 2) if (q[i] != 0) all0 = 0;
        g_flag[0] = all0;  // 1 => int64 source
    }
}
__global__ void convert_kernel(const void* p, int tot) {
    int is64 = g_flag[0];
    for (int i = blockIdx.x * blockDim.x + threadIdx.x; i < tot; i += gridDim.x * blockDim.x)
        g_ei[i] = is64 ? (int)((const long long*)p)[i] : ((const int*)p)[i];
}

// ---------------- GRU: fused, 32 nodes/block, 16 steps, FFMA2 mainloop --------
#define GRU_LDA 36
#define GRU_SMEM ((G3 * HID + 192 * GRU_LDA) * 4)

__global__ void __launch_bounds__(256, 1) gru_kernel(
    const float* __restrict__ X, const float* __restrict__ Wih,
    const float* __restrict__ bih, const float* __restrict__ bhh,
    const float* __restrict__ Whh, float* __restrict__ outh)
{
    extern __shared__ float sm[];
    float* Wsh = sm;              // W_hh [384][128]
    float* aT  = sm + G3 * HID;   // [192][36]: rows 0..63 x_t^T, 64..191 h^T
    const int tid = threadIdx.x;
    const int node0 = blockIdx.x * 32;

    for (int i = tid; i < G3 * HID / 4; i += 256)
        ((float4*)Wsh)[i] = ((const float4*)Whh)[i];
    for (int i = tid; i < 192 * GRU_LDA; i += 256) aT[i] = 0.f;
    __syncthreads();

    const int ng = tid & 7, kg = tid >> 3;
    const int n0 = 4 * ng;

    float br_b[4], bz_b[4], bn_i[4], bn_h[4];
#pragma unroll
    for (int jj = 0; jj < 4; jj++) {
        int p = 4 * kg + jj;
        br_b[jj] = __ldg(&bih[p])       + __ldg(&bhh[p]);
        bz_b[jj] = __ldg(&bih[HID + p]) + __ldg(&bhh[HID + p]);
        bn_i[jj] = __ldg(&bih[2 * HID + p]);
        bn_h[jj] = __ldg(&bhh[2 * HID + p]);
    }

    for (int t = 0; t < SEQ; t++) {
#pragma unroll
        for (int it = 0; it < 8; it++) {
            int idx = tid + it * 256;
            int f = idx & 63, nl = idx >> 6;
            int node = node0 + nl;
            aT[f * GRU_LDA + nl] = (node < NNODES)
                ? X[(size_t)node * (SEQ * FIN) + t * FIN + f] : 0.f;
        }
        __syncthreads();

        // packed accumulators: [jj][node-pair]
        u64 ar2[8], az2[8], ani2[8], anh2[8];
#pragma unroll
        for (int q = 0; q < 8; q++) { ar2[q] = az2[q] = ani2[q] = anh2[q] = 0ull; }

#pragma unroll 1
        for (int k = 0; k < FIN; k += 4) {            // x half (W_ih from L2)
            u64 av[8];
#pragma unroll
            for (int kk = 0; kk < 4; kk++) {
                ulonglong2 tld = *(const ulonglong2*)&aT[(k + kk) * GRU_LDA + n0];
                av[kk * 2] = tld.x; av[kk * 2 + 1] = tld.y;
            }
#pragma unroll
            for (int jj = 0; jj < 4; jj++) {
                int p = 4 * kg + jj;
                float4 wr = __ldg((const float4*)&Wih[(size_t)p * FIN + k]);
                float4 wz = __ldg((const float4*)&Wih[(size_t)(HID + p) * FIN + k]);
                float4 wn = __ldg((const float4*)&Wih[(size_t)(2 * HID + p) * FIN + k]);
#pragma unroll
                for (int kk = 0; kk < 4; kk++) {
                    u64 w0 = dup2(f4c(wr, kk)), w1 = dup2(f4c(wz, kk)), w2 = dup2(f4c(wn, kk));
                    fma2(ar2 [jj * 2], av[kk * 2], w0); fma2(ar2 [jj * 2 + 1], av[kk * 2 + 1], w0);
                    fma2(az2 [jj * 2], av[kk * 2], w1); fma2(az2 [jj * 2 + 1], av[kk * 2 + 1], w1);
                    fma2(ani2[jj * 2], av[kk * 2], w2); fma2(ani2[jj * 2 + 1], av[kk * 2 + 1], w2);
                }
            }
        }
#pragma unroll 1
        for (int k = 0; k < HID; k += 4) {            // h half (W_hh from smem)
            u64 av[8];
#pragma unroll
            for (int kk = 0; kk < 4; kk++) {
                ulonglong2 tld = *(const ulonglong2*)&aT[(64 + k + kk) * GRU_LDA + n0];
                av[kk * 2] = tld.x; av[kk * 2 + 1] = tld.y;
            }
#pragma unroll
            for (int jj = 0; jj < 4; jj++) {
                int p = 4 * kg + jj;
                float4 wr = *(const float4*)&Wsh[(size_t)p * HID + k];
                float4 wz = *(const float4*)&Wsh[(size_t)(HID + p) * HID + k];
                float4 wn = *(const float4*)&Wsh[(size_t)(2 * HID + p) * HID + k];
#pragma unroll
                for (int kk = 0; kk < 4; kk++) {
                    u64 w0 = dup2(f4c(wr, kk)), w1 = dup2(f4c(wz, kk)), w2 = dup2(f4c(wn, kk));
                    fma2(ar2 [jj * 2], av[kk * 2], w0); fma2(ar2 [jj * 2 + 1], av[kk * 2 + 1], w0);
                    fma2(az2 [jj * 2], av[kk * 2], w1); fma2(az2 [jj * 2 + 1], av[kk * 2 + 1], w1);
                    fma2(anh2[jj * 2], av[kk * 2], w2); fma2(anh2[jj * 2 + 1], av[kk * 2 + 1], w2);
                }
            }
        }

        float hnew[16];
#pragma unroll
        for (int jj = 0; jj < 4; jj++) {
            int p = 4 * kg + jj;
            float arr[4], azz[4], ann[4], ahh[4];
            float2 u;
            u = unpk(ar2 [jj * 2]);     arr[0] = u.x; arr[1] = u.y;
            u = unpk(ar2 [jj * 2 + 1]); arr[2] = u.x; arr[3] = u.y;
            u = unpk(az2 [jj * 2]);     azz[0] = u.x; azz[1] = u.y;
            u = unpk(az2 [jj * 2 + 1]); azz[2] = u.x; azz[3] = u.y;
            u = unpk(ani2[jj * 2]);     ann[0] = u.x; ann[1] = u.y;
            u = unpk(ani2[jj * 2 + 1]); ann[2] = u.x; ann[3] = u.y;
            u = unpk(anh2[jj * 2]);     ahh[0] = u.x; ahh[1] = u.y;
            u = unpk(anh2[jj * 2 + 1]); ahh[2] = u.x; ahh[3] = u.y;
#pragma unroll
            for (int i2 = 0; i2 < 4; i2++) {
                float r  = sigmf(arr[i2] + br_b[jj]);
                float z  = sigmf(azz[i2] + bz_b[jj]);
                float nn = tanhfast(ann[i2] + bn_i[jj] + r * (ahh[i2] + bn_h[jj]));
                float hold = aT[(64 + p) * GRU_LDA + n0 + i2];
                hnew[jj * 4 + i2] = (1.f - z) * nn + z * hold;
            }
        }
        __syncthreads();
#pragma unroll
        for (int jj = 0; jj < 4; jj++) {
            int p = 4 * kg + jj;
#pragma unroll
            for (int i2 = 0; i2 < 4; i2++)
                aT[(64 + p) * GRU_LDA + n0 + i2] = hnew[jj * 4 + i2];
        }
        __syncthreads();
    }

#pragma unroll
    for (int it = 0; it < 16; it++) {
        int idx = tid + it * 256;
        int k = idx & 127, nl = idx >> 7;
        int node = node0 + nl;
        if (node < NNODES) outh[(size_t)node * HID + k] = aT[(64 + k) * GRU_LDA + nl];
    }
}

// ---------------- GAT GEMM: h = x @ W^T, 32 nodes/block, FFMA2 ---------------
#define GEMM_SMEM ((HID * HID + HID * GRU_LDA) * 4)

__global__ void __launch_bounds__(256) gemm128_kernel(
    const float* __restrict__ Xin, const float* __restrict__ W, float* __restrict__ Hout)
{
    extern __shared__ float sm[];
    float* Wsh = sm;
    float* xT  = sm + HID * HID;
    const int tid = threadIdx.x;
    const int node0 = blockIdx.x * 32;

    for (int i = tid; i < HID * HID / 4; i += 256)
        ((float4*)Wsh)[i] = ((const float4*)W)[i];
#pragma unroll
    for (int it = 0; it < 16; it++) {
        int idx = tid + it * 256;
        int k = idx & 127, nl = idx >> 7;
        int node = node0 + nl;
        xT[k * GRU_LDA + nl] = (node < NNODES) ? Xin[(size_t)node * HID + k] : 0.f;
    }
    __syncthreads();

    const int ng = tid & 7, og = tid >> 3;
    const int n0 = 4 * ng, o0 = 4 * og;
    u64 acc2[8];
#pragma unroll
    for (int q = 0; q < 8; q++) acc2[q] = 0ull;

#pragma unroll 1
    for (int k = 0; k < HID; k += 4) {
        u64 av[8];
#pragma unroll
        for (int kk = 0; kk < 4; kk++) {
            ulonglong2 tld = *(const ulonglong2*)&xT[(k + kk) * GRU_LDA + n0];
            av[kk * 2] = tld.x; av[kk * 2 + 1] = tld.y;
        }
#pragma unroll
        for (int jj = 0; jj < 4; jj++) {
            float4 wv = *(const float4*)&Wsh[(size_t)(o0 + jj) * HID + k];
#pragma unroll
            for (int kk = 0; kk < 4; kk++) {
                u64 wd = dup2(f4c(wv, kk));
                fma2(acc2[jj * 2], av[kk * 2], wd);
                fma2(acc2[jj * 2 + 1], av[kk * 2 + 1], wd);
            }
        }
    }
    float acc[16];
#pragma unroll
    for (int jj = 0; jj < 4; jj++) {
        float2 u;
        u = unpk(acc2[jj * 2]);     acc[jj * 4 + 0] = u.x; acc[jj * 4 + 1] = u.y;
        u = unpk(acc2[jj * 2 + 1]); acc[jj * 4 + 2] = u.x; acc[jj * 4 + 3] = u.y;
    }
#pragma unroll
    for (int i2 = 0; i2 < 4; i2++) {
        int node = node0 + n0 + i2;
        if (node < NNODES)
            *(float4*)&Hout[(size_t)node * HID + o0] =
                make_float4(acc[0 + i2], acc[4 + i2], acc[8 + i2], acc[12 + i2]);
    }
}

// ---------------- attention prep + edge passes ----------------
__global__ void att_kernel(const float* __restrict__ h1, const float* __restrict__ asrc,
                           const float* __restrict__ adst, int n)
{
    int g = blockIdx.x * blockDim.x + threadIdx.x;
    if (g >= n * NHEAD) return;
    int node = g >> 2, hh = g & 3;
    const float* hp = h1 + (size_t)node * HID + hh * 32;
    float s = 0.f, d = 0.f;
#pragma unroll
    for (int c = 0; c < 32; c += 4) {
        float4 hv = *(const float4*)&hp[c];
        float4 sv = __ldg((const float4*)&asrc[hh * 32 + c]);
        float4 dv = __ldg((const float4*)&adst[hh * 32 + c]);
        s += hv.x * sv.x + hv.y * sv.y + hv.z * sv.z + hv.w * sv.w;
        d += hv.x * dv.x + hv.y * dv.y + hv.z * dv.z + hv.w * dv.w;
    }
    g_as[g] = s; g_ad[g] = d;
    g_m[g] = __int_as_float(0xff800000u);
    g_den[g] = 0.f;
}

__global__ void zero_kernel(float* p, int n) {
    int i = blockIdx.x * blockDim.x + threadIdx.x;
    if (i < n) p[i] = 0.f;
}

__global__ void edge_max_kernel(int E, int n) {
    int tot = E + n;
    for (int i = blockIdx.x * blockDim.x + threadIdx.x; i < tot; i += gridDim.x * blockDim.x) {
        int s, d;
        if (i < E) { s = g_ei[i]; d = g_ei[E + i]; } else { s = d = i - E; }
        float4 a = *(const float4*)&g_as[s * 4];
        float4 b = *(const float4*)&g_ad[d * 4];
        float4 ev = make_float4(lrelu(a.x + b.x), lrelu(a.y + b.y),
                                lrelu(a.z + b.z), lrelu(a.w + b.w));
        *(float4*)&g_e[(size_t)i * 4] = ev;
        atomicMaxF(&g_m[d * 4 + 0], ev.x);
        atomicMaxF(&g_m[d * 4 + 1], ev.y);
        atomicMaxF(&g_m[d * 4 + 2], ev.z);
        atomicMaxF(&g_m[d * 4 + 3], ev.w);
    }
}

__global__ void edge_expsum_kernel(int E, int n) {
    int tot = E + n;
    for (int i = blockIdx.x * blockDim.x + threadIdx.x; i < tot; i += gridDim.x * blockDim.x) {
        int d = (i < E) ? g_ei[E + i] : (i - E);
        float4 ev = *(const float4*)&g_e[(size_t)i * 4];
        float4 mm = *(const float4*)&g_m[d * 4];
        float4 ex = make_float4(__expf(ev.x - mm.x), __expf(ev.y - mm.y),
                                __expf(ev.z - mm.z), __expf(ev.w - mm.w));
        *(float4*)&g_e[(size_t)i * 4] = ex;
        redAdd4(&g_den[d * 4], ex);
    }
}

__global__ void rden_kernel(int n4) {
    int i = blockIdx.x * blockDim.x + threadIdx.x;
    if (i < n4) g_den[i] = 1.f / (g_den[i] + 1e-16f);
}

__global__ void edge_scatter_kernel(const float* __restrict__ h1, float* __restrict__ out,
                                    int E, int n)
{
    int lane = threadIdx.x & 31;
    int w = (blockIdx.x * blockDim.x + threadIdx.x) >> 5;
    int nwarp = (gridDim.x * blockDim.x) >> 5;
    int tot = E + n;
    for (int i = w; i < tot; i += nwarp) {
        int s, d;
        if (i < E) { s = g_ei[i]; d = g_ei[E + i]; } else { s = d = i - E; }
        float4 ex = *(const float4*)&g_e[(size_t)i * 4];
        float4 rd = *(const float4*)&g_den[d * 4];
        float alpha = f4c(make_float4(ex.x * rd.x, ex.y * rd.y, ex.z * rd.z, ex.w * rd.w),
                          lane >> 3);
        float4 hv = *(const float4*)&h1[(size_t)s * HID + lane * 4];
        redAdd4(&out[(size_t)d * HID + lane * 4],
                make_float4(hv.x * alpha, hv.y * alpha, hv.z * alpha, hv.w * alpha));
    }
}

__global__ void finish_kernel(const float* __restrict__ acc, const float* __restrict__ b,
                              float* __restrict__ xout, int tot)
{
    int i = blockIdx.x * blockDim.x + threadIdx.x;
    if (i < tot) {
        float v = acc[i] + __ldg(&b[i & 127]);
        xout[i] = v > 0.f ? v : expm1f(v);
    }
}

__global__ void clf_kernel(const float* __restrict__ x, const float* __restrict__ wgt,
                           const float* __restrict__ b, float* __restrict__ out, int n)
{
    int lane = threadIdx.x & 31;
    int w = (blockIdx.x * blockDim.x + threadIdx.x) >> 5;
    if (w >= n) return;
    float4 xv = *(const float4*)&x[(size_t)w * HID + lane * 4];
    float4 wv = __ldg((const float4*)&wgt[lane * 4]);
    float s = xv.x * wv.x + xv.y * wv.y + xv.z * wv.z + xv.w * wv.w;
#pragma unroll
    for (int o = 16; o; o >>= 1) s += __shfl_xor_sync(0xffffffffu, s, o);
    if (lane == 0) out[w] = 1.f / (1.f + expf(-(s + __ldg(b))));
}

// ---------------- host side ----------------
static void run_gat(const float* xin, const float* w, const float* asrc, const float* adst,
                    const float* b, float* xout, float* h1, float* accb, int E, int n)
{
    gemm128_kernel<<<(n + 31) / 32, 256, GEMM_SMEM>>>(xin, w, h1);
    att_kernel<<<(n * NHEAD + 255) / 256, 256>>>(h1, asrc, adst, n);
    zero_kernel<<<(n * HID + 255) / 256, 256>>>(accb, n * HID);
    edge_max_kernel<<<2048, 256>>>(E, n);
    edge_expsum_kernel<<<2048, 256>>>(E, n);
    rden_kernel<<<(n * NHEAD + 255) / 256, 256>>>(n * NHEAD);
    edge_scatter_kernel<<<8192, 256>>>(h1, accb, E, n);
    finish_kernel<<<(n * HID + 255) / 256, 256>>>(accb, b, xout, n * HID);
}

extern "C" void kernel_launch(void* const* d_in, const int* in_sizes, int n_in,
                              void* d_out, int out_size)
{
    (void)in_sizes; (void)n_in; (void)out_size;
    const float* X    = (const float*)d_in[0];
    const void*  EIp  = d_in[1];
    const float* Wih  = (const float*)d_in[2];
    const float* Whh  = (const float*)d_in[3];
    const float* bih  = (const float*)d_in[4];
    const float* bhh  = (const float*)d_in[5];
    const float* g1w  = (const float*)d_in[6];
    const float* g1as = (const float*)d_in[7];
    const float* g1ad = (const float*)d_in[8];
    const float* g1b  = (const float*)d_in[9];
    const float* g2w  = (const float*)d_in[10];
    const float* g2as = (const float*)d_in[11];
    const float* g2ad = (const float*)d_in[12];
    const float* g2b  = (const float*)d_in[13];
    const float* cw   = (const float*)d_in[14];
    const float* cb   = (const float*)d_in[15];
    float* out = (float*)d_out;

    cudaFuncSetAttribute(gru_kernel, cudaFuncAttributeMaxDynamicSharedMemorySize, GRU_SMEM);
    cudaFuncSetAttribute(gemm128_kernel, cudaFuncAttributeMaxDynamicSharedMemorySize, GEMM_SMEM);

    float *x0, *x1, *h1, *acc;
    cudaGetSymbolAddress((void**)&x0,  g_x0);
    cudaGetSymbolAddress((void**)&x1,  g_x1);
    cudaGetSymbolAddress((void**)&h1,  g_h1);
    cudaGetSymbolAddress((void**)&acc, g_acc);

    detect_kernel<<<1, 32>>>(EIp);
    convert_kernel<<<2048, 256>>>(EIp, 2 * ECONST);

    gru_kernel<<<(NNODES + 31) / 32, 256, GRU_SMEM>>>(X, Wih, bih, bhh, Whh, x0);

    run_gat(x0, g1w, g1as, g1ad, g1b, x1, h1, acc, ECONST, NNODES);
    run_gat(x1, g2w, g2as, g2ad, g2b, x0, h1, acc, ECONST, NNODES);

    clf_kernel<<<(NNODES * 32 + 255) / 256, 256>>>(x0, cw, cb, out, NNODES);
}

// round 8
// speedup vs baseline: 1.3917x; 1.3737x over previous
#include <cuda_runtime.h>
#include <cuda_fp16.h>
#include <cstdint>
#include <cstddef>

#define NNODES 50000
#define SEQ    16
#define FIN    64
#define HID    128
#define G3     384
#define NHEAD  4
#define ECONST 1600000
#define ETOT   (ECONST + NNODES)

// ---------------- scratch (device globals; no runtime allocation) -------------
__device__ float g_x0 [(size_t)NNODES * HID];
__device__ float g_x1 [(size_t)NNODES * HID];
__device__ float g_h1 [(size_t)NNODES * HID];
__device__ float g_acc[(size_t)NNODES * HID];
__device__ float g_as [NNODES * NHEAD];
__device__ float g_ad [NNODES * NHEAD];
__device__ float g_m  [NNODES * NHEAD];
__device__ float g_den[NNODES * NHEAD];
__device__ float g_e  [(size_t)ETOT * NHEAD];
__device__ int   g_ei [2 * ECONST];
__device__ int   g_flag[1];
__device__ float g_gi [(size_t)NNODES * SEQ * G3];   // X @ W_ih^T
__device__ uint4 g_fih4[6144];    // Wih frags: 2 splits x 4kt x 48ntg x 32 lanes x uint2 = 98304 B
__device__ uint4 g_fhh4[12288];   // Whh frags: 2 splits x 8kt x 48ntg x 32 lanes x uint2 = 196608 B

// ---------------- helpers ----------------
__device__ __forceinline__ float f4c(const float4 v, int i) {
    switch (i & 3) { case 0: return v.x; case 1: return v.y; case 2: return v.z; default: return v.w; }
}
__device__ __forceinline__ float sigmf(float x) { return 1.f / (1.f + __expf(-x)); }
__device__ __forceinline__ float tanhfast(float x) { return 2.f / (1.f + __expf(-2.f * x)) - 1.f; }
__device__ __forceinline__ float lrelu(float x) { return x >= 0.f ? x : 0.2f * x; }
__device__ __forceinline__ void atomicMaxF(float* a, float v) {
    if (v >= 0.f) atomicMax((int*)a, __float_as_int(v));
    else          atomicMin((unsigned int*)a, __float_as_uint(v));
}
__device__ __forceinline__ void redAdd4(float* a, float4 v) {
    asm volatile("red.global.add.v4.f32 [%0], {%1,%2,%3,%4};"
                 :: "l"(a), "f"(v.x), "f"(v.y), "f"(v.z), "f"(v.w) : "memory");
}
__device__ __forceinline__ uint32_t smem_u32(const void* p) {
    uint32_t a;
    asm("{ .reg .u64 t; cvta.to.shared.u64 t, %1; cvt.u32.u64 %0, t; }" : "=r"(a) : "l"(p));
    return a;
}
__device__ __forceinline__ uint32_t packh2(float a, float b) {
    __half2 p = __halves2half2(__float2half_rn(a), __float2half_rn(b));
    return *(uint32_t*)&p;
}
__device__ __forceinline__ uint32_t packh2_lo(float a, float b) {
    float ar = a - __half2float(__float2half_rn(a));
    float br = b - __half2float(__float2half_rn(b));
    return packh2(ar, br);
}
__device__ __forceinline__ void mma16816(float* d, const uint32_t* a, const uint32_t* b) {
    asm volatile("mma.sync.aligned.m16n8k16.row.col.f32.f16.f16.f32 "
        "{%0,%1,%2,%3}, {%4,%5,%6,%7}, {%8,%9}, {%0,%1,%2,%3};"
        : "+f"(d[0]), "+f"(d[1]), "+f"(d[2]), "+f"(d[3])
        : "r"(a[0]), "r"(a[1]), "r"(a[2]), "r"(a[3]), "r"(b[0]), "r"(b[1]));
}
__device__ __forceinline__ void ldsm4(uint32_t* r, uint32_t addr) {
    asm volatile("ldmatrix.sync.aligned.m8n8.x4.shared.b16 {%0,%1,%2,%3}, [%4];"
        : "=r"(r[0]), "=r"(r[1]), "=r"(r[2]), "=r"(r[3]) : "r"(addr));
}

// ---------------- edge dtype detect + convert ----------------
__global__ void detect_kernel(const void* p) {
    if (threadIdx.x == 0) {
        const int* q = (const int*)p;
        int all0 = 1;
        for (int i = 1; i < 64; i += 2) if (q[i] != 0) all0 = 0;
        g_flag[0] = all0;
    }
}
__global__ void convert_kernel(const void* p, int tot) {
    int is64 = g_flag[0];
    for (int i = blockIdx.x * blockDim.x + threadIdx.x; i < tot; i += gridDim.x * blockDim.x)
        g_ei[i] = is64 ? (int)((const long long*)p)[i] : ((const int*)p)[i];
}

// ---------------- weight fragment precompute ----------------
__global__ void fragprep_kernel(const float* __restrict__ Wih, const float* __restrict__ Whh) {
    int e = blockIdx.x * blockDim.x + threadIdx.x;
    if (e < 12288) {
        int lane = e & 31, tile = e >> 5;
        int ntg = tile % 48, kt = (tile / 48) & 3, split = tile / 192;
        int n = ntg * 8 + (lane >> 2), k = kt * 16 + (lane & 3) * 2;
        const float* wr = Wih + (size_t)n * FIN;
        float w0 = wr[k], w1 = wr[k + 1], w2 = wr[k + 8], w3 = wr[k + 9];
        uint2 v;
        if (split == 0) { v.x = packh2(w0, w1); v.y = packh2(w2, w3); }
        else            { v.x = packh2_lo(w0, w1); v.y = packh2_lo(w2, w3); }
        ((uint2*)g_fih4)[tile * 32 + lane] = v;
    }
    if (e < 24576) {
        int lane = e & 31, tile = e >> 5;
        int ntg = tile % 48, kt = (tile / 48) & 7, split = tile / 384;
        int n = ntg * 8 + (lane >> 2), k = kt * 16 + (lane & 3) * 2;
        const float* wr = Whh + (size_t)n * HID;
        float w0 = wr[k], w1 = wr[k + 1], w2 = wr[k + 8], w3 = wr[k + 9];
        uint2 v;
        if (split == 0) { v.x = packh2(w0, w1); v.y = packh2(w2, w3); }
        else            { v.x = packh2_lo(w0, w1); v.y = packh2_lo(w2, w3); }
        ((uint2*)g_fhh4)[tile * 32 + lane] = v;
    }
}

// ============ xgemm: gi = X @ Wih^T via mma.sync, 64 rows/block ===============
// smem: [0,98304) frags | [98304,+9216) X_hi [64][72]fp16 | [107520,+9216) X_lo
#define XG_SMEM (98304 + 2 * 9216)

__global__ void __launch_bounds__(256, 1) xg_kernel(const float* __restrict__ X) {
    extern __shared__ char smx[];
    const int tid = threadIdx.x, wid = tid >> 5, lane = tid & 31;
    const int warpM = wid >> 2, warpN = wid & 3;
    const int row0 = blockIdx.x * 64;

    for (int i = tid; i < 6144; i += 256) ((uint4*)smx)[i] = g_fih4[i];
    for (int i = tid; i < 2048; i += 256) {
        int row = i >> 5, cp = (i & 31) * 2;
        float2 v = *(const float2*)&X[(size_t)(row0 + row) * FIN + cp];
        uint32_t off = (uint32_t)row * 144 + (uint32_t)cp * 2;
        *(uint32_t*)(smx + 98304 + off)  = packh2(v.x, v.y);
        *(uint32_t*)(smx + 107520 + off) = packh2_lo(v.x, v.y);
    }
    __syncthreads();

    uint32_t sb = smem_u32(smx);
    const int rowl = ((lane >> 3) & 1) * 8 + (lane & 7), khalf = lane >> 4;
    uint32_t ab[2][2];
#pragma unroll
    for (int s = 0; s < 2; s++)
#pragma unroll
        for (int mt = 0; mt < 2; mt++)
            ab[s][mt] = sb + 98304 + s * 9216
                      + (uint32_t)(warpM * 32 + mt * 16 + rowl) * 144 + khalf * 16;

    float acc[96];
#pragma unroll
    for (int i = 0; i < 96; i++) acc[i] = 0.f;

#pragma unroll 1
    for (int kt = 0; kt < 4; kt++) {
        uint32_t Ah[2][4], Al[2][4];
        ldsm4(Ah[0], ab[0][0] + kt * 32);
        ldsm4(Ah[1], ab[0][1] + kt * 32);
        ldsm4(Al[0], ab[1][0] + kt * 32);
        ldsm4(Al[1], ab[1][1] + kt * 32);
#pragma unroll
        for (int nt = 0; nt < 12; nt++) {
            int ntg = warpN * 12 + nt;
            const char* fb = smx + ((kt * 48 + ntg) << 8) + (lane << 3);
            uint2 bh = *(const uint2*)fb;
            uint2 bl = *(const uint2*)(fb + 49152);
            float* a0 = &acc[(0 * 12 + nt) * 4];
            float* a1 = &acc[(1 * 12 + nt) * 4];
            mma16816(a0, Ah[0], &bh.x); mma16816(a1, Ah[1], &bh.x);
            mma16816(a0, Ah[0], &bl.x); mma16816(a1, Ah[1], &bl.x);
            mma16816(a0, Al[0], &bh.x); mma16816(a1, Al[1], &bh.x);
        }
    }
#pragma unroll
    for (int mt = 0; mt < 2; mt++)
#pragma unroll
        for (int nt = 0; nt < 12; nt++)
#pragma unroll
            for (int rh = 0; rh < 2; rh++) {
                int row = row0 + warpM * 32 + mt * 16 + (lane >> 2) + rh * 8;
                int col = warpN * 96 + nt * 8 + (lane & 3) * 2;
                const float* a = &acc[(mt * 12 + nt) * 4];
                *(float2*)&g_gi[(size_t)row * G3 + col] = make_float2(a[rh * 2], a[rh * 2 + 1]);
            }
}

// ============ recurrent GRU via mma.sync, 64 nodes/block ======================
// smem: [0,196608) Whh frags (hi|lo) | [196608,+17408) h_hi [64][136]fp16 | [214016,+17408) h_lo
#define GM_SMEM (196608 + 2 * 17408)

__global__ void __launch_bounds__(256, 1) grum_kernel(
    const float* __restrict__ bih, const float* __restrict__ bhh, float* __restrict__ outh)
{
    extern __shared__ char smx[];
    const int tid = threadIdx.x, wid = tid >> 5, lane = tid & 31;
    const int warpM = wid >> 2, warpN = wid & 3;
    const int node0 = blockIdx.x * 64;

    for (int i = tid; i < 12288; i += 256) ((uint4*)smx)[i] = g_fhh4[i];
    {
        uint32_t* hz = (uint32_t*)(smx + 196608);
        for (int i = tid; i < 8704; i += 256) hz[i] = 0;
    }
    float br[8], bz[8], bni[8], bnh[8];
#pragma unroll
    for (int q = 0; q < 8; q++) {
        int c = warpN * 32 + (q >> 1) * 8 + (lane & 3) * 2 + (q & 1);
        br[q]  = __ldg(&bih[c]) + __ldg(&bhh[c]);
        bz[q]  = __ldg(&bih[128 + c]) + __ldg(&bhh[128 + c]);
        bni[q] = __ldg(&bih[256 + c]);
        bnh[q] = __ldg(&bhh[256 + c]);
    }
    __syncthreads();

    uint32_t sb = smem_u32(smx);
    const int rowl = ((lane >> 3) & 1) * 8 + (lane & 7), khalf = lane >> 4;
    uint32_t ab[2][2];
#pragma unroll
    for (int s = 0; s < 2; s++)
#pragma unroll
        for (int mt = 0; mt < 2; mt++)
            ab[s][mt] = sb + 196608 + s * 17408
                      + (uint32_t)(warpM * 32 + mt * 16 + rowl) * 272 + khalf * 16;

    float hold[32];
#pragma unroll
    for (int i = 0; i < 32; i++) hold[i] = 0.f;
    float acc[96];

    for (int t = 0; t < SEQ; t++) {
#pragma unroll
        for (int i = 0; i < 96; i++) acc[i] = 0.f;
#pragma unroll 1
        for (int kt = 0; kt < 8; kt++) {
            uint32_t Ah[2][4], Al[2][4];
            ldsm4(Ah[0], ab[0][0] + kt * 32);
            ldsm4(Ah[1], ab[0][1] + kt * 32);
            ldsm4(Al[0], ab[1][0] + kt * 32);
            ldsm4(Al[1], ab[1][1] + kt * 32);
#pragma unroll
            for (int g = 0; g < 3; g++)
#pragma unroll
                for (int nt = 0; nt < 4; nt++) {
                    int ntg = g * 16 + warpN * 4 + nt;
                    const char* fb = smx + ((kt * 48 + ntg) << 8) + (lane << 3);
                    uint2 bh = *(const uint2*)fb;
                    uint2 bl = *(const uint2*)(fb + 98304);
                    float* a0 = &acc[((0 * 3 + g) * 4 + nt) * 4];
                    float* a1 = &acc[((1 * 3 + g) * 4 + nt) * 4];
                    mma16816(a0, Ah[0], &bh.x); mma16816(a1, Ah[1], &bh.x);
                    mma16816(a0, Ah[0], &bl.x); mma16816(a1, Ah[1], &bl.x);
                    mma16816(a0, Al[0], &bh.x); mma16816(a1, Al[1], &bh.x);
                }
        }
        __syncthreads();   // all warps finished reading h via ldmatrix

#pragma unroll
        for (int mt = 0; mt < 2; mt++)
#pragma unroll
            for (int nt = 0; nt < 4; nt++) {
                int c0 = warpN * 32 + nt * 8 + (lane & 3) * 2;
#pragma unroll
                for (int rh = 0; rh < 2; rh++) {
                    int row = warpM * 32 + mt * 16 + (lane >> 2) + rh * 8;
                    int node = node0 + row;
                    bool valid = node < NNODES;
                    const float* gp = g_gi + ((size_t)(valid ? node : 0) * SEQ + t) * G3;
                    float2 gr = valid ? *(const float2*)&gp[c0]       : make_float2(0.f, 0.f);
                    float2 gz = valid ? *(const float2*)&gp[128 + c0] : make_float2(0.f, 0.f);
                    float2 gn = valid ? *(const float2*)&gp[256 + c0] : make_float2(0.f, 0.f);
                    float h2[2];
#pragma unroll
                    for (int j = 0; j < 2; j++) {
                        int d = rh * 2 + j, q = nt * 2 + j;
                        float rv = sigmf(acc[((mt * 3 + 0) * 4 + nt) * 4 + d] + (j ? gr.y : gr.x) + br[q]);
                        float zv = sigmf(acc[((mt * 3 + 1) * 4 + nt) * 4 + d] + (j ? gz.y : gz.x) + bz[q]);
                        float nv = tanhfast((j ? gn.y : gn.x) + bni[q]
                                  + rv * (acc[((mt * 3 + 2) * 4 + nt) * 4 + d] + bnh[q]));
                        int hx = (mt * 4 + nt) * 4 + d;
                        float hv = (1.f - zv) * nv + zv * hold[hx];
                        hold[hx] = hv;
                        h2[j] = hv;
                    }
                    uint32_t off = (uint32_t)row * 272 + (uint32_t)c0 * 2;
                    *(uint32_t*)(smx + 196608 + off) = packh2(h2[0], h2[1]);
                    *(uint32_t*)(smx + 214016 + off) = packh2_lo(h2[0], h2[1]);
                    if (t == SEQ - 1 && valid)
                        *(float2*)&outh[(size_t)node * HID + c0] = make_float2(h2[0], h2[1]);
                }
            }
        __syncthreads();   // h stores visible before next step's ldmatrix
    }
}

// ---------------- GAT GEMM: h = x @ W^T, fp32 (unchanged, passing) ------------
#define GRU_LDA 36
#define GEMM_SMEM ((HID * HID + HID * GRU_LDA) * 4)

__global__ void __launch_bounds__(256) gemm128_kernel(
    const float* __restrict__ Xin, const float* __restrict__ W, float* __restrict__ Hout)
{
    extern __shared__ float sm[];
    float* Wsh = sm;
    float* xT  = sm + HID * HID;
    const int tid = threadIdx.x;
    const int node0 = blockIdx.x * 32;

    for (int i = tid; i < HID * HID / 4; i += 256)
        ((float4*)Wsh)[i] = ((const float4*)W)[i];
#pragma unroll
    for (int it = 0; it < 16; it++) {
        int idx = tid + it * 256;
        int k = idx & 127, nl = idx >> 7;
        int node = node0 + nl;
        xT[k * GRU_LDA + nl] = (node < NNODES) ? Xin[(size_t)node * HID + k] : 0.f;
    }
    __syncthreads();

    const int ng = tid & 7, og = tid >> 3;
    const int n0 = 4 * ng, o0 = 4 * og;
    float acc[16];
#pragma unroll
    for (int q = 0; q < 16; q++) acc[q] = 0.f;

#pragma unroll 1
    for (int k = 0; k < HID; k += 4) {
        float4 av[4], wv[4];
#pragma unroll
        for (int kk = 0; kk < 4; kk++) av[kk] = *(const float4*)&xT[(k + kk) * GRU_LDA + n0];
#pragma unroll
        for (int jj = 0; jj < 4; jj++) wv[jj] = *(const float4*)&Wsh[(size_t)(o0 + jj) * HID + k];
#pragma unroll
        for (int jj = 0; jj < 4; jj++)
#pragma unroll
            for (int kk = 0; kk < 4; kk++) {
                float w = f4c(wv[jj], kk);
#pragma unroll
                for (int i2 = 0; i2 < 4; i2++)
                    acc[jj * 4 + i2] = fmaf(f4c(av[kk], i2), w, acc[jj * 4 + i2]);
            }
    }
#pragma unroll
    for (int i2 = 0; i2 < 4; i2++) {
        int node = node0 + n0 + i2;
        if (node < NNODES)
            *(float4*)&Hout[(size_t)node * HID + o0] =
                make_float4(acc[0 + i2], acc[4 + i2], acc[8 + i2], acc[12 + i2]);
    }
}

// ---------------- attention prep + edge passes (unchanged, passing) -----------
__global__ void att_kernel(const float* __restrict__ h1, const float* __restrict__ asrc,
                           const float* __restrict__ adst, int n)
{
    int g = blockIdx.x * blockDim.x + threadIdx.x;
    if (g >= n * NHEAD) return;
    int node = g >> 2, hh = g & 3;
    const float* hp = h1 + (size_t)node * HID + hh * 32;
    float s = 0.f, d = 0.f;
#pragma unroll
    for (int c = 0; c < 32; c += 4) {
        float4 hv = *(const float4*)&hp[c];
        float4 sv = __ldg((const float4*)&asrc[hh * 32 + c]);
        float4 dv = __ldg((const float4*)&adst[hh * 32 + c]);
        s += hv.x * sv.x + hv.y * sv.y + hv.z * sv.z + hv.w * sv.w;
        d += hv.x * dv.x + hv.y * dv.y + hv.z * dv.z + hv.w * dv.w;
    }
    g_as[g] = s; g_ad[g] = d;
    g_m[g] = __int_as_float(0xff800000u);
    g_den[g] = 0.f;
}

__global__ void zero_kernel(float* p, int n) {
    int i = blockIdx.x * blockDim.x + threadIdx.x;
    if (i < n) p[i] = 0.f;
}

__global__ void edge_max_kernel(int E, int n) {
    int tot = E + n;
    for (int i = blockIdx.x * blockDim.x + threadIdx.x; i < tot; i += gridDim.x * blockDim.x) {
        int s, d;
        if (i < E) { s = g_ei[i]; d = g_ei[E + i]; } else { s = d = i - E; }
        float4 a = *(const float4*)&g_as[s * 4];
        float4 b = *(const float4*)&g_ad[d * 4];
        float4 ev = make_float4(lrelu(a.x + b.x), lrelu(a.y + b.y),
                                lrelu(a.z + b.z), lrelu(a.w + b.w));
        *(float4*)&g_e[(size_t)i * 4] = ev;
        atomicMaxF(&g_m[d * 4 + 0], ev.x);
        atomicMaxF(&g_m[d * 4 + 1], ev.y);
        atomicMaxF(&g_m[d * 4 + 2], ev.z);
        atomicMaxF(&g_m[d * 4 + 3], ev.w);
    }
}

__global__ void edge_expsum_kernel(int E, int n) {
    int tot = E + n;
    for (int i = blockIdx.x * blockDim.x + threadIdx.x; i < tot; i += gridDim.x * blockDim.x) {
        int d = (i < E) ? g_ei[E + i] : (i - E);
        float4 ev = *(const float4*)&g_e[(size_t)i * 4];
        float4 mm = *(const float4*)&g_m[d * 4];
        float4 ex = make_float4(__expf(ev.x - mm.x), __expf(ev.y - mm.y),
                                __expf(ev.z - mm.z), __expf(ev.w - mm.w));
        *(float4*)&g_e[(size_t)i * 4] = ex;
        redAdd4(&g_den[d * 4], ex);
    }
}

__global__ void rden_kernel(int n4) {
    int i = blockIdx.x * blockDim.x + threadIdx.x;
    if (i < n4) g_den[i] = 1.f / (g_den[i] + 1e-16f);
}

__global__ void edge_scatter_kernel(const float* __restrict__ h1, float* __restrict__ out,
                                    int E, int n)
{
    int lane = threadIdx.x & 31;
    int w = (blockIdx.x * blockDim.x + threadIdx.x) >> 5;
    int nwarp = (gridDim.x * blockDim.x) >> 5;
    int tot = E + n;
    for (int i = w; i < tot; i += nwarp) {
        int s, d;
        if (i < E) { s = g_ei[i]; d = g_ei[E + i]; } else { s = d = i - E; }
        float4 ex = *(const float4*)&g_e[(size_t)i * 4];
        float4 rd = *(const float4*)&g_den[d * 4];
        float alpha = f4c(make_float4(ex.x * rd.x, ex.y * rd.y, ex.z * rd.z, ex.w * rd.w),
                          lane >> 3);
        float4 hv = *(const float4*)&h1[(size_t)s * HID + lane * 4];
        redAdd4(&out[(size_t)d * HID + lane * 4],
                make_float4(hv.x * alpha, hv.y * alpha, hv.z * alpha, hv.w * alpha));
    }
}

__global__ void finish_kernel(const float* __restrict__ acc, const float* __restrict__ b,
                              float* __restrict__ xout, int tot)
{
    int i = blockIdx.x * blockDim.x + threadIdx.x;
    if (i < tot) {
        float v = acc[i] + __ldg(&b[i & 127]);
        xout[i] = v > 0.f ? v : expm1f(v);
    }
}

__global__ void clf_kernel(const float* __restrict__ x, const float* __restrict__ wgt,
                           const float* __restrict__ b, float* __restrict__ out, int n)
{
    int lane = threadIdx.x & 31;
    int w = (blockIdx.x * blockDim.x + threadIdx.x) >> 5;
    if (w >= n) return;
    float4 xv = *(const float4*)&x[(size_t)w * HID + lane * 4];
    float4 wv = __ldg((const float4*)&wgt[lane * 4]);
    float s = xv.x * wv.x + xv.y * wv.y + xv.z * wv.z + xv.w * wv.w;
#pragma unroll
    for (int o = 16; o; o >>= 1) s += __shfl_xor_sync(0xffffffffu, s, o);
    if (lane == 0) out[w] = 1.f / (1.f + expf(-(s + __ldg(b))));
}

// ---------------- host side ----------------
static void run_gat(const float* xin, const float* w, const float* asrc, const float* adst,
                    const float* b, float* xout, float* h1, float* accb, int E, int n)
{
    gemm128_kernel<<<(n + 31) / 32, 256, GEMM_SMEM>>>(xin, w, h1);
    att_kernel<<<(n * NHEAD + 255) / 256, 256>>>(h1, asrc, adst, n);
    zero_kernel<<<(n * HID + 255) / 256, 256>>>(accb, n * HID);
    edge_max_kernel<<<2048, 256>>>(E, n);
    edge_expsum_kernel<<<2048, 256>>>(E, n);
    rden_kernel<<<(n * NHEAD + 255) / 256, 256>>>(n * NHEAD);
    edge_scatter_kernel<<<8192, 256>>>(h1, accb, E, n);
    finish_kernel<<<(n * HID + 255) / 256, 256>>>(accb, b, xout, n * HID);
}

extern "C" void kernel_launch(void* const* d_in, const int* in_sizes, int n_in,
                              void* d_out, int out_size)
{
    (void)in_sizes; (void)n_in; (void)out_size;
    const float* X    = (const float*)d_in[0];
    const void*  EIp  = d_in[1];
    const float* Wih  = (const float*)d_in[2];
    const float* Whh  = (const float*)d_in[3];
    const float* bih  = (const float*)d_in[4];
    const float* bhh  = (const float*)d_in[5];
    const float* g1w  = (const float*)d_in[6];
    const float* g1as = (const float*)d_in[7];
    const float* g1ad = (const float*)d_in[8];
    const float* g1b  = (const float*)d_in[9];
    const float* g2w  = (const float*)d_in[10];
    const float* g2as = (const float*)d_in[11];
    const float* g2ad = (const float*)d_in[12];
    const float* g2b  = (const float*)d_in[13];
    const float* cw   = (const float*)d_in[14];
    const float* cb   = (const float*)d_in[15];
    float* out = (float*)d_out;

    cudaFuncSetAttribute(xg_kernel,   cudaFuncAttributeMaxDynamicSharedMemorySize, XG_SMEM);
    cudaFuncSetAttribute(grum_kernel, cudaFuncAttributeMaxDynamicSharedMemorySize, GM_SMEM);
    cudaFuncSetAttribute(gemm128_kernel, cudaFuncAttributeMaxDynamicSharedMemorySize, GEMM_SMEM);

    float *x0, *x1, *h1, *acc;
    cudaGetSymbolAddress((void**)&x0,  g_x0);
    cudaGetSymbolAddress((void**)&x1,  g_x1);
    cudaGetSymbolAddress((void**)&h1,  g_h1);
    cudaGetSymbolAddress((void**)&acc, g_acc);

    detect_kernel<<<1, 32>>>(EIp);
    convert_kernel<<<2048, 256>>>(EIp, 2 * ECONST);
    fragprep_kernel<<<96, 256>>>(Wih, Whh);

    xg_kernel<<<(NNODES * SEQ) / 64, 256, XG_SMEM>>>(X);
    grum_kernel<<<(NNODES + 63) / 64, 256, GM_SMEM>>>(bih, bhh, x0);

    run_gat(x0, g1w, g1as, g1ad, g1b, x1, h1, acc, ECONST, NNODES);
    run_gat(x1, g2w, g2as, g2ad, g2b, x0, h1, acc, ECONST, NNODES);

    clf_kernel<<<(NNODES * 32 + 255) / 256, 256>>>(x0, cw, cb, out, NNODES);
}

// round 9
// speedup vs baseline: 1.9813x; 1.4237x over previous
#include <cuda_runtime.h>
#include <cuda_fp16.h>
#include <cstdint>
#include <cstddef>

#define NNODES 50000
#define SEQ    16
#define FIN    64
#define HID    128
#define G3     384
#define NHEAD  4
#define ECONST 1600000
#define ETOT   (ECONST + NNODES)

// ---------------- scratch (device globals; no runtime allocation) -------------
__device__ float g_x0 [(size_t)NNODES * HID];
__device__ float g_x1 [(size_t)NNODES * HID];
__device__ float g_h1 [(size_t)NNODES * HID];
__device__ float g_acc[(size_t)NNODES * HID];
__device__ float g_as [NNODES * NHEAD];
__device__ float g_ad [NNODES * NHEAD];
__device__ float g_m  [NNODES * NHEAD];
__device__ float g_den[NNODES * NHEAD];
__device__ float g_e  [(size_t)ETOT * NHEAD];
__device__ int   g_ei [2 * ECONST];
__device__ int   g_flag[1];
__device__ uint4 g_fih4[6144];    // Wih frags: 2 splits x 4kt x 48ntg x 32 lanes x uint2
__device__ uint4 g_fhh4[12288];   // Whh frags: 2 splits x 8kt x 48ntg x 32 lanes x uint2

// ---------------- helpers ----------------
__device__ __forceinline__ float f4c(const float4 v, int i) {
    switch (i & 3) { case 0: return v.x; case 1: return v.y; case 2: return v.z; default: return v.w; }
}
__device__ __forceinline__ float sigmf(float x) { return 1.f / (1.f + __expf(-x)); }
__device__ __forceinline__ float tanhfast(float x) { return 2.f / (1.f + __expf(-2.f * x)) - 1.f; }
__device__ __forceinline__ float lrelu(float x) { return x >= 0.f ? x : 0.2f * x; }
__device__ __forceinline__ void atomicMaxF(float* a, float v) {
    if (v >= 0.f) atomicMax((int*)a, __float_as_int(v));
    else          atomicMin((unsigned int*)a, __float_as_uint(v));
}
__device__ __forceinline__ void redAdd4(float* a, float4 v) {
    asm volatile("red.global.add.v4.f32 [%0], {%1,%2,%3,%4};"
                 :: "l"(a), "f"(v.x), "f"(v.y), "f"(v.z), "f"(v.w) : "memory");
}
__device__ __forceinline__ uint32_t smem_u32(const void* p) {
    uint32_t a;
    asm("{ .reg .u64 t; cvta.to.shared.u64 t, %1; cvt.u32.u64 %0, t; }" : "=r"(a) : "l"(p));
    return a;
}
__device__ __forceinline__ uint32_t packh2(float a, float b) {
    __half2 p = __halves2half2(__float2half_rn(a), __float2half_rn(b));
    return *(uint32_t*)&p;
}
__device__ __forceinline__ uint32_t packh2_lo(float a, float b) {
    float ar = a - __half2float(__float2half_rn(a));
    float br = b - __half2float(__float2half_rn(b));
    return packh2(ar, br);
}
__device__ __forceinline__ void mma16816(float* d, const uint32_t* a, const uint32_t* b) {
    asm volatile("mma.sync.aligned.m16n8k16.row.col.f32.f16.f16.f32 "
        "{%0,%1,%2,%3}, {%4,%5,%6,%7}, {%8,%9}, {%0,%1,%2,%3};"
        : "+f"(d[0]), "+f"(d[1]), "+f"(d[2]), "+f"(d[3])
        : "r"(a[0]), "r"(a[1]), "r"(a[2]), "r"(a[3]), "r"(b[0]), "r"(b[1]));
}
__device__ __forceinline__ void ldsm4(uint32_t* r, uint32_t addr) {
    asm volatile("ldmatrix.sync.aligned.m8n8.x4.shared.b16 {%0,%1,%2,%3}, [%4];"
        : "=r"(r[0]), "=r"(r[1]), "=r"(r[2]), "=r"(r[3]) : "r"(addr));
}

// ---------------- edge dtype detect + convert ----------------
__global__ void detect_kernel(const void* p) {
    if (threadIdx.x == 0) {
        const int* q = (const int*)p;
        int all0 = 1;
        for (int i = 1; i < 64; i += 2) if (q[i] != 0) all0 = 0;
        g_flag[0] = all0;
    }
}
__global__ void convert_kernel(const void* p, int tot) {
    int is64 = g_flag[0];
    for (int i = blockIdx.x * blockDim.x + threadIdx.x; i < tot; i += gridDim.x * blockDim.x)
        g_ei[i] = is64 ? (int)((const long long*)p)[i] : ((const int*)p)[i];
}

// ---------------- weight fragment precompute ----------------
__global__ void fragprep_kernel(const float* __restrict__ Wih, const float* __restrict__ Whh) {
    int e = blockIdx.x * blockDim.x + threadIdx.x;
    if (e < 12288) {
        int lane = e & 31, tile = e >> 5;
        int ntg = tile % 48, kt = (tile / 48) & 3, split = tile / 192;
        int n = ntg * 8 + (lane >> 2), k = kt * 16 + (lane & 3) * 2;
        const float* wr = Wih + (size_t)n * FIN;
        float w0 = wr[k], w1 = wr[k + 1], w2 = wr[k + 8], w3 = wr[k + 9];
        uint2 v;
        if (split == 0) { v.x = packh2(w0, w1); v.y = packh2(w2, w3); }
        else            { v.x = packh2_lo(w0, w1); v.y = packh2_lo(w2, w3); }
        ((uint2*)g_fih4)[tile * 32 + lane] = v;
    }
    if (e < 24576) {
        int lane = e & 31, tile = e >> 5;
        int ntg = tile % 48, kt = (tile / 48) & 7, split = tile / 384;
        int n = ntg * 8 + (lane >> 2), k = kt * 16 + (lane & 3) * 2;
        const float* wr = Whh + (size_t)n * HID;
        float w0 = wr[k], w1 = wr[k + 1], w2 = wr[k + 8], w3 = wr[k + 9];
        uint2 v;
        if (split == 0) { v.x = packh2(w0, w1); v.y = packh2(w2, w3); }
        else            { v.x = packh2_lo(w0, w1); v.y = packh2_lo(w2, w3); }
        ((uint2*)g_fhh4)[tile * 32 + lane] = v;
    }
}

// ============ fused GRU: x-GEMM + h-GEMM + cell, 32 nodes/block ===============
// smem: [0,196608) Whh frags (hi|lo) | h_hi @196608 (32x272B) | h_lo @205312
//       | x_hi @214016 (32x144B) | x_lo @218624   -> total 223232 B
#define HF_HHI 196608
#define HF_HLO 205312
#define HF_XHI 214016
#define HF_XLO 218624
#define GF_SMEM 223232

__global__ void __launch_bounds__(256, 1) gru_fused_kernel(
    const float* __restrict__ X, const float* __restrict__ bih,
    const float* __restrict__ bhh, float* __restrict__ outh)
{
    extern __shared__ char smx[];
    const int tid = threadIdx.x, w = tid >> 5, lane = tid & 31;
    const int node0 = blockIdx.x * 32;

    // stage Whh frags (hi+lo) into smem
    for (int i = tid; i < 12288; i += 256) ((uint4*)smx)[i] = g_fhh4[i];
    // zero h hi/lo buffers (17408 B)
    {
        uint32_t* hz = (uint32_t*)(smx + HF_HHI);
        for (int i = tid; i < 4352; i += 256) hz[i] = 0;
    }
    // biases: thread's 4 cols per gate: c = w*16 + nt*8 + (lane&3)*2 + j
    float br[4], bz[4], bni[4], bnh[4];
#pragma unroll
    for (int q = 0; q < 4; q++) {
        int c = w * 16 + (q >> 1) * 8 + (lane & 3) * 2 + (q & 1);
        br[q]  = __ldg(&bih[c]) + __ldg(&bhh[c]);
        bz[q]  = __ldg(&bih[128 + c]) + __ldg(&bhh[128 + c]);
        bni[q] = __ldg(&bih[256 + c]);
        bnh[q] = __ldg(&bhh[256 + c]);
    }
    __syncthreads();

    uint32_t sb = smem_u32(smx);
    const int rowl = ((lane >> 3) & 1) * 8 + (lane & 7), khalf = lane >> 4;
    uint32_t abh[2][2], abx[2][2];   // [split][mt]
#pragma unroll
    for (int s = 0; s < 2; s++)
#pragma unroll
        for (int mt = 0; mt < 2; mt++) {
            abh[s][mt] = sb + (s ? HF_HLO : HF_HHI) + (uint32_t)(mt * 16 + rowl) * 272 + khalf * 16;
            abx[s][mt] = sb + (s ? HF_XLO : HF_XHI) + (uint32_t)(mt * 16 + rowl) * 144 + khalf * 16;
        }

    float hold[16];
#pragma unroll
    for (int i = 0; i < 16; i++) hold[i] = 0.f;
    // acc slots: 0=r, 1=z, 2=n_x, 3=n_h ; index ((mt*4+g)*2+nt)*4 + d
    float acc[64];

    const uint2* fih = (const uint2*)g_fih4;

    for (int t = 0; t < SEQ; t++) {
        // stage x_t: 32 nodes x 64 floats -> hi/lo fp16
        {
            int i4 = tid * 4;
#pragma unroll
            for (int q = 0; q < 4; q++) {
                int i = i4 + q;                  // 0..1023
                int row = i >> 5, cp = (i & 31) * 2;
                int node = node0 + row;
                float2 v = (node < NNODES)
                    ? *(const float2*)&X[(size_t)node * (SEQ * FIN) + t * FIN + cp]
                    : make_float2(0.f, 0.f);
                uint32_t off = (uint32_t)row * 144 + (uint32_t)cp * 2;
                *(uint32_t*)(smx + HF_XHI + off) = packh2(v.x, v.y);
                *(uint32_t*)(smx + HF_XLO + off) = packh2_lo(v.x, v.y);
            }
        }
        __syncthreads();   // x_t staged; h(t-1) stores visible to all warps

#pragma unroll
        for (int i = 0; i < 64; i++) acc[i] = 0.f;

        // ---- h-side: K=128, Whh frags from smem ----
#pragma unroll 1
        for (int kt = 0; kt < 8; kt++) {
            uint32_t Ah[2][4], Al[2][4];
            ldsm4(Ah[0], abh[0][0] + kt * 32);
            ldsm4(Ah[1], abh[0][1] + kt * 32);
            ldsm4(Al[0], abh[1][0] + kt * 32);
            ldsm4(Al[1], abh[1][1] + kt * 32);
#pragma unroll
            for (int g = 0; g < 3; g++)
#pragma unroll
                for (int nt = 0; nt < 2; nt++) {
                    int ntg = g * 16 + w * 2 + nt;
                    const char* fb = smx + ((kt * 48 + ntg) << 8) + (lane << 3);
                    uint2 bh = *(const uint2*)fb;
                    uint2 bl = *(const uint2*)(fb + 98304);
                    int gs = (g == 2) ? 3 : g;
                    float* a0 = &acc[((0 * 4 + gs) * 2 + nt) * 4];
                    float* a1 = &acc[((1 * 4 + gs) * 2 + nt) * 4];
                    mma16816(a0, Ah[0], &bh.x); mma16816(a1, Ah[1], &bh.x);
                    mma16816(a0, Ah[0], &bl.x); mma16816(a1, Ah[1], &bl.x);
                    mma16816(a0, Al[0], &bh.x); mma16816(a1, Al[1], &bh.x);
                }
        }
        // ---- x-side: K=64, Wih frags from global (L2-resident) ----
#pragma unroll 1
        for (int kt = 0; kt < 4; kt++) {
            uint32_t Ah[2][4], Al[2][4];
            ldsm4(Ah[0], abx[0][0] + kt * 32);
            ldsm4(Ah[1], abx[0][1] + kt * 32);
            ldsm4(Al[0], abx[1][0] + kt * 32);
            ldsm4(Al[1], abx[1][1] + kt * 32);
#pragma unroll
            for (int g = 0; g < 3; g++)
#pragma unroll
                for (int nt = 0; nt < 2; nt++) {
                    int ntg = g * 16 + w * 2 + nt;
                    uint2 bh = __ldg(&fih[((kt * 48 + ntg) << 5) + lane]);
                    uint2 bl = __ldg(&fih[((192 + kt * 48 + ntg) << 5) + lane]);
                    float* a0 = &acc[((0 * 4 + g) * 2 + nt) * 4];
                    float* a1 = &acc[((1 * 4 + g) * 2 + nt) * 4];
                    mma16816(a0, Ah[0], &bh.x); mma16816(a1, Ah[1], &bh.x);
                    mma16816(a0, Ah[0], &bl.x); mma16816(a1, Ah[1], &bl.x);
                    mma16816(a0, Al[0], &bh.x); mma16816(a1, Al[1], &bh.x);
                }
        }
        __syncthreads();   // all warps done reading h/x smem

        // ---- GRU cell + h store ----
#pragma unroll
        for (int mt = 0; mt < 2; mt++)
#pragma unroll
            for (int nt = 0; nt < 2; nt++) {
                int c0 = w * 16 + nt * 8 + (lane & 3) * 2;
#pragma unroll
                for (int rh = 0; rh < 2; rh++) {
                    int row = mt * 16 + (lane >> 2) + rh * 8;
                    int node = node0 + row;
                    float h2[2];
#pragma unroll
                    for (int j = 0; j < 2; j++) {
                        int d = rh * 2 + j, q = nt * 2 + j;
                        float rv = sigmf(acc[((mt * 4 + 0) * 2 + nt) * 4 + d] + br[q]);
                        float zv = sigmf(acc[((mt * 4 + 1) * 2 + nt) * 4 + d] + bz[q]);
                        float nv = tanhfast(acc[((mt * 4 + 2) * 2 + nt) * 4 + d] + bni[q]
                                  + rv * (acc[((mt * 4 + 3) * 2 + nt) * 4 + d] + bnh[q]));
                        int hx = ((mt * 2 + nt) * 2 + rh) * 2 + j;
                        float hv = (1.f - zv) * nv + zv * hold[hx];
                        hold[hx] = hv;
                        h2[j] = hv;
                    }
                    uint32_t off = (uint32_t)row * 272 + (uint32_t)c0 * 2;
                    *(uint32_t*)(smx + HF_HHI + off) = packh2(h2[0], h2[1]);
                    *(uint32_t*)(smx + HF_HLO + off) = packh2_lo(h2[0], h2[1]);
                    if (t == SEQ - 1 && node < NNODES)
                        *(float2*)&outh[(size_t)node * HID + c0] = make_float2(h2[0], h2[1]);
                }
            }
    }
}

// ---------------- GAT GEMM: h = x @ W^T, fp32 (unchanged, passing) ------------
#define GRU_LDA 36
#define GEMM_SMEM ((HID * HID + HID * GRU_LDA) * 4)

__global__ void __launch_bounds__(256) gemm128_kernel(
    const float* __restrict__ Xin, const float* __restrict__ W, float* __restrict__ Hout)
{
    extern __shared__ float sm[];
    float* Wsh = sm;
    float* xT  = sm + HID * HID;
    const int tid = threadIdx.x;
    const int node0 = blockIdx.x * 32;

    for (int i = tid; i < HID * HID / 4; i += 256)
        ((float4*)Wsh)[i] = ((const float4*)W)[i];
#pragma unroll
    for (int it = 0; it < 16; it++) {
        int idx = tid + it * 256;
        int k = idx & 127, nl = idx >> 7;
        int node = node0 + nl;
        xT[k * GRU_LDA + nl] = (node < NNODES) ? Xin[(size_t)node * HID + k] : 0.f;
    }
    __syncthreads();

    const int ng = tid & 7, og = tid >> 3;
    const int n0 = 4 * ng, o0 = 4 * og;
    float acc[16];
#pragma unroll
    for (int q = 0; q < 16; q++) acc[q] = 0.f;

#pragma unroll 1
    for (int k = 0; k < HID; k += 4) {
        float4 av[4], wv[4];
#pragma unroll
        for (int kk = 0; kk < 4; kk++) av[kk] = *(const float4*)&xT[(k + kk) * GRU_LDA + n0];
#pragma unroll
        for (int jj = 0; jj < 4; jj++) wv[jj] = *(const float4*)&Wsh[(size_t)(o0 + jj) * HID + k];
#pragma unroll
        for (int jj = 0; jj < 4; jj++)
#pragma unroll
            for (int kk = 0; kk < 4; kk++) {
                float wq = f4c(wv[jj], kk);
#pragma unroll
                for (int i2 = 0; i2 < 4; i2++)
                    acc[jj * 4 + i2] = fmaf(f4c(av[kk], i2), wq, acc[jj * 4 + i2]);
            }
    }
#pragma unroll
    for (int i2 = 0; i2 < 4; i2++) {
        int node = node0 + n0 + i2;
        if (node < NNODES)
            *(float4*)&Hout[(size_t)node * HID + o0] =
                make_float4(acc[0 + i2], acc[4 + i2], acc[8 + i2], acc[12 + i2]);
    }
}

// ---------------- attention prep + edge passes (unchanged, passing) -----------
__global__ void att_kernel(const float* __restrict__ h1, const float* __restrict__ asrc,
                           const float* __restrict__ adst, int n)
{
    int g = blockIdx.x * blockDim.x + threadIdx.x;
    if (g >= n * NHEAD) return;
    int node = g >> 2, hh = g & 3;
    const float* hp = h1 + (size_t)node * HID + hh * 32;
    float s = 0.f, d = 0.f;
#pragma unroll
    for (int c = 0; c < 32; c += 4) {
        float4 hv = *(const float4*)&hp[c];
        float4 sv = __ldg((const float4*)&asrc[hh * 32 + c]);
        float4 dv = __ldg((const float4*)&adst[hh * 32 + c]);
        s += hv.x * sv.x + hv.y * sv.y + hv.z * sv.z + hv.w * sv.w;
        d += hv.x * dv.x + hv.y * dv.y + hv.z * dv.z + hv.w * dv.w;
    }
    g_as[g] = s; g_ad[g] = d;
    g_m[g] = __int_as_float(0xff800000u);
    g_den[g] = 0.f;
}

__global__ void zero_kernel(float* p, int n) {
    int i = blockIdx.x * blockDim.x + threadIdx.x;
    if (i < n) p[i] = 0.f;
}

__global__ void edge_max_kernel(int E, int n) {
    int tot = E + n;
    for (int i = blockIdx.x * blockDim.x + threadIdx.x; i < tot; i += gridDim.x * blockDim.x) {
        int s, d;
        if (i < E) { s = g_ei[i]; d = g_ei[E + i]; } else { s = d = i - E; }
        float4 a = *(const float4*)&g_as[s * 4];
        float4 b = *(const float4*)&g_ad[d * 4];
        float4 ev = make_float4(lrelu(a.x + b.x), lrelu(a.y + b.y),
                                lrelu(a.z + b.z), lrelu(a.w + b.w));
        *(float4*)&g_e[(size_t)i * 4] = ev;
        atomicMaxF(&g_m[d * 4 + 0], ev.x);
        atomicMaxF(&g_m[d * 4 + 1], ev.y);
        atomicMaxF(&g_m[d * 4 + 2], ev.z);
        atomicMaxF(&g_m[d * 4 + 3], ev.w);
    }
}

__global__ void edge_expsum_kernel(int E, int n) {
    int tot = E + n;
    for (int i = blockIdx.x * blockDim.x + threadIdx.x; i < tot; i += gridDim.x * blockDim.x) {
        int d = (i < E) ? g_ei[E + i] : (i - E);
        float4 ev = *(const float4*)&g_e[(size_t)i * 4];
        float4 mm = *(const float4*)&g_m[d * 4];
        float4 ex = make_float4(__expf(ev.x - mm.x), __expf(ev.y - mm.y),
                                __expf(ev.z - mm.z), __expf(ev.w - mm.w));
        *(float4*)&g_e[(size_t)i * 4] = ex;
        redAdd4(&g_den[d * 4], ex);
    }
}

__global__ void rden_kernel(int n4) {
    int i = blockIdx.x * blockDim.x + threadIdx.x;
    if (i < n4) g_den[i] = 1.f / (g_den[i] + 1e-16f);
}

__global__ void edge_scatter_kernel(const float* __restrict__ h1, float* __restrict__ out,
                                    int E, int n)
{
    int lane = threadIdx.x & 31;
    int w = (blockIdx.x * blockDim.x + threadIdx.x) >> 5;
    int nwarp = (gridDim.x * blockDim.x) >> 5;
    int tot = E + n;
    for (int i = w; i < tot; i += nwarp) {
        int s, d;
        if (i < E) { s = g_ei[i]; d = g_ei[E + i]; } else { s = d = i - E; }
        float4 ex = *(const float4*)&g_e[(size_t)i * 4];
        float4 rd = *(const float4*)&g_den[d * 4];
        float alpha = f4c(make_float4(ex.x * rd.x, ex.y * rd.y, ex.z * rd.z, ex.w * rd.w),
                          lane >> 3);
        float4 hv = *(const float4*)&h1[(size_t)s * HID + lane * 4];
        redAdd4(&out[(size_t)d * HID + lane * 4],
                make_float4(hv.x * alpha, hv.y * alpha, hv.z * alpha, hv.w * alpha));
    }
}

__global__ void finish_kernel(const float* __restrict__ acc, const float* __restrict__ b,
                              float* __restrict__ xout, int tot)
{
    int i = blockIdx.x * blockDim.x + threadIdx.x;
    if (i < tot) {
        float v = acc[i] + __ldg(&b[i & 127]);
        xout[i] = v > 0.f ? v : expm1f(v);
    }
}

__global__ void clf_kernel(const float* __restrict__ x, const float* __restrict__ wgt,
                           const float* __restrict__ b, float* __restrict__ out, int n)
{
    int lane = threadIdx.x & 31;
    int w = (blockIdx.x * blockDim.x + threadIdx.x) >> 5;
    if (w >= n) return;
    float4 xv = *(const float4*)&x[(size_t)w * HID + lane * 4];
    float4 wv = __ldg((const float4*)&wgt[lane * 4]);
    float s = xv.x * wv.x + xv.y * wv.y + xv.z * wv.z + xv.w * wv.w;
#pragma unroll
    for (int o = 16; o; o >>= 1) s += __shfl_xor_sync(0xffffffffu, s, o);
    if (lane == 0) out[w] = 1.f / (1.f + expf(-(s + __ldg(b))));
}

// ---------------- host side ----------------
static void run_gat(const float* xin, const float* w, const float* asrc, const float* adst,
                    const float* b, float* xout, float* h1, float* accb, int E, int n)
{
    gemm128_kernel<<<(n + 31) / 32, 256, GEMM_SMEM>>>(xin, w, h1);
    att_kernel<<<(n * NHEAD + 255) / 256, 256>>>(h1, asrc, adst, n);
    zero_kernel<<<(n * HID + 255) / 256, 256>>>(accb, n * HID);
    edge_max_kernel<<<2048, 256>>>(E, n);
    edge_expsum_kernel<<<2048, 256>>>(E, n);
    rden_kernel<<<(n * NHEAD + 255) / 256, 256>>>(n * NHEAD);
    edge_scatter_kernel<<<8192, 256>>>(h1, accb, E, n);
    finish_kernel<<<(n * HID + 255) / 256, 256>>>(accb, b, xout, n * HID);
}

extern "C" void kernel_launch(void* const* d_in, const int* in_sizes, int n_in,
                              void* d_out, int out_size)
{
    (void)in_sizes; (void)n_in; (void)out_size;
    const float* X    = (const float*)d_in[0];
    const void*  EIp  = d_in[1];
    const float* Wih  = (const float*)d_in[2];
    const float* Whh  = (const float*)d_in[3];
    const float* bih  = (const float*)d_in[4];
    const float* bhh  = (const float*)d_in[5];
    const float* g1w  = (const float*)d_in[6];
    const float* g1as = (const float*)d_in[7];
    const float* g1ad = (const float*)d_in[8];
    const float* g1b  = (const float*)d_in[9];
    const float* g2w  = (const float*)d_in[10];
    const float* g2as = (const float*)d_in[11];
    const float* g2ad = (const float*)d_in[12];
    const float* g2b  = (const float*)d_in[13];
    const float* cw   = (const float*)d_in[14];
    const float* cb   = (const float*)d_in[15];
    float* out = (float*)d_out;

    cudaFuncSetAttribute(gru_fused_kernel, cudaFuncAttributeMaxDynamicSharedMemorySize, GF_SMEM);
    cudaFuncSetAttribute(gemm128_kernel, cudaFuncAttributeMaxDynamicSharedMemorySize, GEMM_SMEM);

    float *x0, *x1, *h1, *acc;
    cudaGetSymbolAddress((void**)&x0,  g_x0);
    cudaGetSymbolAddress((void**)&x1,  g_x1);
    cudaGetSymbolAddress((void**)&h1,  g_h1);
    cudaGetSymbolAddress((void**)&acc, g_acc);

    detect_kernel<<<1, 32>>>(EIp);
    convert_kernel<<<2048, 256>>>(EIp, 2 * ECONST);
    fragprep_kernel<<<96, 256>>>(Wih, Whh);

    gru_fused_kernel<<<(NNODES + 31) / 32, 256, GF_SMEM>>>(X, bih, bhh, x0);

    run_gat(x0, g1w, g1as, g1ad, g1b, x1, h1, acc, ECONST, NNODES);
    run_gat(x1, g2w, g2as, g2ad, g2b, x0, h1, acc, ECONST, NNODES);

    clf_kernel<<<(NNODES * 32 + 255) / 256, 256>>>(x0, cw, cb, out, NNODES);
}

// round 12
// speedup vs baseline: 2.2673x; 1.1444x over previous
#include <cuda_runtime.h>
#include <cuda_fp16.h>
#include <cstdint>
#include <cstddef>

#define NNODES 50000
#define SEQ    16
#define FIN    64
#define HID    128
#define G3     384
#define NHEAD  4
#define ECONST 1600000
#define ETOT   (ECONST + NNODES)

// ---------------- scratch (device globals; no runtime allocation) -------------
__device__ float g_x0 [(size_t)NNODES * HID];
__device__ float g_x1 [(size_t)NNODES * HID];
__device__ float g_h1 [(size_t)NNODES * HID];
__device__ float g_acc[(size_t)NNODES * HID];
__device__ float g_as [NNODES * NHEAD];
__device__ float g_ad [NNODES * NHEAD];
__device__ float g_den[NNODES * NHEAD];
__device__ float g_e  [(size_t)ETOT * NHEAD];
__device__ int   g_ei [2 * ECONST];
__device__ int   g_flag[1];
__device__ uint4 g_fih4[6144];    // Wih frags: 2 splits x 4kt x 48ntg x 32 lanes x uint2
__device__ uint4 g_fhh4[12288];   // Whh frags: 2 splits x 8kt x 48ntg x 32 lanes x uint2
__device__ uint4 g_fgat[8192];    // GAT W frags: 2 layers x (2 splits x 8kt x 16ntg) x 32 x uint2

// ---------------- helpers ----------------
__device__ __forceinline__ float f4c(const float4 v, int i) {
    switch (i & 3) { case 0: return v.x; case 1: return v.y; case 2: return v.z; default: return v.w; }
}
__device__ __forceinline__ float sigmf(float x) { return 1.f / (1.f + __expf(-x)); }
__device__ __forceinline__ float tanhfast(float x) { return 2.f / (1.f + __expf(-2.f * x)) - 1.f; }
__device__ __forceinline__ float lrelu(float x) { return x >= 0.f ? x : 0.2f * x; }
__device__ __forceinline__ void redAdd4(float* a, float4 v) {
    asm volatile("red.global.add.v4.f32 [%0], {%1,%2,%3,%4};"
                 :: "l"(a), "f"(v.x), "f"(v.y), "f"(v.z), "f"(v.w) : "memory");
}
__device__ __forceinline__ uint32_t smem_u32(const void* p) {
    uint32_t a;
    asm("{ .reg .u64 t; cvta.to.shared.u64 t, %1; cvt.u32.u64 %0, t; }" : "=r"(a) : "l"(p));
    return a;
}
__device__ __forceinline__ uint32_t packh2(float a, float b) {
    __half2 p = __halves2half2(__float2half_rn(a), __float2half_rn(b));
    return *(uint32_t*)&p;
}
__device__ __forceinline__ uint32_t packh2_lo(float a, float b) {
    float ar = a - __half2float(__float2half_rn(a));
    float br = b - __half2float(__float2half_rn(b));
    return packh2(ar, br);
}
__device__ __forceinline__ void mma16816(float* d, const uint32_t* a, const uint32_t* b) {
    asm volatile("mma.sync.aligned.m16n8k16.row.col.f32.f16.f16.f32 "
        "{%0,%1,%2,%3}, {%4,%5,%6,%7}, {%8,%9}, {%0,%1,%2,%3};"
        : "+f"(d[0]), "+f"(d[1]), "+f"(d[2]), "+f"(d[3])
        : "r"(a[0]), "r"(a[1]), "r"(a[2]), "r"(a[3]), "r"(b[0]), "r"(b[1]));
}
__device__ __forceinline__ void ldsm4(uint32_t* r, uint32_t addr) {
    asm volatile("ldmatrix.sync.aligned.m8n8.x4.shared.b16 {%0,%1,%2,%3}, [%4];"
        : "=r"(r[0]), "=r"(r[1]), "=r"(r[2]), "=r"(r[3]) : "r"(addr));
}

// ---------------- edge dtype detect + convert ----------------
__global__ void detect_kernel(const void* p) {
    if (threadIdx.x == 0) {
        const int* q = (const int*)p;
        int all0 = 1;
        for (int i = 1; i < 64; i += 2) if (q[i] != 0) all0 = 0;
        g_flag[0] = all0;
    }
}
__global__ void convert_kernel(const void* p, int tot) {
    int is64 = g_flag[0];
    for (int i = blockIdx.x * blockDim.x + threadIdx.x; i < tot; i += gridDim.x * blockDim.x)
        g_ei[i] = is64 ? (int)((const long long*)p)[i] : ((const int*)p)[i];
}

// ---------------- weight fragment precompute ----------------
__global__ void fragprep_kernel(const float* __restrict__ Wih, const float* __restrict__ Whh) {
    int e = blockIdx.x * blockDim.x + threadIdx.x;
    if (e < 12288) {
        int lane = e & 31, tile = e >> 5;
        int ntg = tile % 48, kt = (tile / 48) & 3, split = tile / 192;
        int n = ntg * 8 + (lane >> 2), k = kt * 16 + (lane & 3) * 2;
        const float* wr = Wih + (size_t)n * FIN;
        float w0 = wr[k], w1 = wr[k + 1], w2 = wr[k + 8], w3 = wr[k + 9];
        uint2 v;
        if (split == 0) { v.x = packh2(w0, w1); v.y = packh2(w2, w3); }
        else            { v.x = packh2_lo(w0, w1); v.y = packh2_lo(w2, w3); }
        ((uint2*)g_fih4)[tile * 32 + lane] = v;
    }
    if (e < 24576) {
        int lane = e & 31, tile = e >> 5;
        int ntg = tile % 48, kt = (tile / 48) & 7, split = tile / 384;
        int n = ntg * 8 + (lane >> 2), k = kt * 16 + (lane & 3) * 2;
        const float* wr = Whh + (size_t)n * HID;
        float w0 = wr[k], w1 = wr[k + 1], w2 = wr[k + 8], w3 = wr[k + 9];
        uint2 v;
        if (split == 0) { v.x = packh2(w0, w1); v.y = packh2(w2, w3); }
        else            { v.x = packh2_lo(w0, w1); v.y = packh2_lo(w2, w3); }
        ((uint2*)g_fhh4)[tile * 32 + lane] = v;
    }
}

// GAT weight frags: per layer, 2 splits x 8kt x 16ntg tiles (256 tiles/layer)
__global__ void fragprep_gat_kernel(const float* __restrict__ g1w, const float* __restrict__ g2w) {
    int e = blockIdx.x * blockDim.x + threadIdx.x;
    if (e >= 16384) return;
    int lane = e & 31, tile = e >> 5;          // tile < 512
    int layer = tile >> 8, tl = tile & 255;
    int ntg = tl & 15, kt = (tl >> 4) & 7, split = tl >> 7;
    const float* W = layer ? g2w : g1w;
    int n = ntg * 8 + (lane >> 2), k = kt * 16 + (lane & 3) * 2;
    const float* wr = W + (size_t)n * HID;
    float w0 = wr[k], w1 = wr[k + 1], w2 = wr[k + 8], w3 = wr[k + 9];
    uint2 v;
    if (split == 0) { v.x = packh2(w0, w1); v.y = packh2(w2, w3); }
    else            { v.x = packh2_lo(w0, w1); v.y = packh2_lo(w2, w3); }
    ((uint2*)g_fgat)[tile * 32 + lane] = v;
}

// ============ fused GRU: x-GEMM + h-GEMM + cell, 32 nodes/block ===============
// smem: [0,196608) Whh frags (hi|lo) | h_hi @196608 (32x272B) | h_lo @205312
//       | x_hi @214016 (32x144B) | x_lo @218624   -> total 223232 B
#define HF_HHI 196608
#define HF_HLO 205312
#define HF_XHI 214016
#define HF_XLO 218624
#define GF_SMEM 223232

__global__ void __launch_bounds__(256, 1) gru_fused_kernel(
    const float* __restrict__ X, const float* __restrict__ bih,
    const float* __restrict__ bhh, float* __restrict__ outh)
{
    extern __shared__ char smx[];
    const int tid = threadIdx.x, w = tid >> 5, lane = tid & 31;
    const int node0 = blockIdx.x * 32;

    for (int i = tid; i < 12288; i += 256) ((uint4*)smx)[i] = g_fhh4[i];
    {
        uint32_t* hz = (uint32_t*)(smx + HF_HHI);
        for (int i = tid; i < 4352; i += 256) hz[i] = 0;
    }
    float br[4], bz[4], bni[4], bnh[4];
#pragma unroll
    for (int q = 0; q < 4; q++) {
        int c = w * 16 + (q >> 1) * 8 + (lane & 3) * 2 + (q & 1);
        br[q]  = __ldg(&bih[c]) + __ldg(&bhh[c]);
        bz[q]  = __ldg(&bih[128 + c]) + __ldg(&bhh[128 + c]);
        bni[q] = __ldg(&bih[256 + c]);
        bnh[q] = __ldg(&bhh[256 + c]);
    }

    // per-thread x-staging geometry: 4 float2 per thread
    const int i4 = tid * 4;

    // stage x_0 into smem
    {
#pragma unroll
        for (int q = 0; q < 4; q++) {
            int i = i4 + q;
            int row = i >> 5, cp = (i & 31) * 2;
            int node = node0 + row;
            float2 v = (node < NNODES)
                ? *(const float2*)&X[(size_t)node * (SEQ * FIN) + 0 * FIN + cp]
                : make_float2(0.f, 0.f);
            uint32_t off = (uint32_t)row * 144 + (uint32_t)cp * 2;
            *(uint32_t*)(smx + HF_XHI + off) = packh2(v.x, v.y);
            *(uint32_t*)(smx + HF_XLO + off) = packh2_lo(v.x, v.y);
        }
    }

    uint32_t sb = smem_u32(smx);
    const int rowl = ((lane >> 3) & 1) * 8 + (lane & 7), khalf = lane >> 4;
    uint32_t abh[2][2], abx[2][2];
#pragma unroll
    for (int s = 0; s < 2; s++)
#pragma unroll
        for (int mt = 0; mt < 2; mt++) {
            abh[s][mt] = sb + (s ? HF_HLO : HF_HHI) + (uint32_t)(mt * 16 + rowl) * 272 + khalf * 16;
            abx[s][mt] = sb + (s ? HF_XLO : HF_XHI) + (uint32_t)(mt * 16 + rowl) * 144 + khalf * 16;
        }

    float hold[16];
#pragma unroll
    for (int i = 0; i < 16; i++) hold[i] = 0.f;
    float acc[64];

    const uint2* fih = (const uint2*)g_fih4;

    for (int t = 0; t < SEQ; t++) {
        __syncthreads();   // x_t + h(t-1) stores visible

        // prefetch x_{t+1} into regs (hides DRAM latency under the mma phase)
        float2 px[4];
        if (t < SEQ - 1) {
#pragma unroll
            for (int q = 0; q < 4; q++) {
                int i = i4 + q;
                int row = i >> 5, cp = (i & 31) * 2;
                int node = node0 + row;
                px[q] = (node < NNODES)
                    ? *(const float2*)&X[(size_t)node * (SEQ * FIN) + (t + 1) * FIN + cp]
                    : make_float2(0.f, 0.f);
            }
        }

#pragma unroll
        for (int i = 0; i < 64; i++) acc[i] = 0.f;

        // ---- h-side: K=128, Whh frags from smem ----
#pragma unroll 1
        for (int kt = 0; kt < 8; kt++) {
            uint32_t Ah[2][4], Al[2][4];
            ldsm4(Ah[0], abh[0][0] + kt * 32);
            ldsm4(Ah[1], abh[0][1] + kt * 32);
            ldsm4(Al[0], abh[1][0] + kt * 32);
            ldsm4(Al[1], abh[1][1] + kt * 32);
#pragma unroll
            for (int g = 0; g < 3; g++)
#pragma unroll
                for (int nt = 0; nt < 2; nt++) {
                    int ntg = g * 16 + w * 2 + nt;
                    const char* fb = smx + ((kt * 48 + ntg) << 8) + (lane << 3);
                    uint2 bh = *(const uint2*)fb;
                    uint2 bl = *(const uint2*)(fb + 98304);
                    int gs = (g == 2) ? 3 : g;
                    float* a0 = &acc[((0 * 4 + gs) * 2 + nt) * 4];
                    float* a1 = &acc[((1 * 4 + gs) * 2 + nt) * 4];
                    mma16816(a0, Ah[0], &bh.x); mma16816(a1, Ah[1], &bh.x);
                    mma16816(a0, Ah[0], &bl.x); mma16816(a1, Ah[1], &bl.x);
                    mma16816(a0, Al[0], &bh.x); mma16816(a1, Al[1], &bh.x);
                }
        }
        // ---- x-side: K=64, Wih frags from global (L2-resident) ----
#pragma unroll 1
        for (int kt = 0; kt < 4; kt++) {
            uint32_t Ah[2][4], Al[2][4];
            ldsm4(Ah[0], abx[0][0] + kt * 32);
            ldsm4(Ah[1], abx[0][1] + kt * 32);
            ldsm4(Al[0], abx[1][0] + kt * 32);
            ldsm4(Al[1], abx[1][1] + kt * 32);
#pragma unroll
            for (int g = 0; g < 3; g++)
#pragma unroll
                for (int nt = 0; nt < 2; nt++) {
                    int ntg = g * 16 + w * 2 + nt;
                    uint2 bh = __ldg(&fih[((kt * 48 + ntg) << 5) + lane]);
                    uint2 bl = __ldg(&fih[((192 + kt * 48 + ntg) << 5) + lane]);
                    float* a0 = &acc[((0 * 4 + g) * 2 + nt) * 4];
                    float* a1 = &acc[((1 * 4 + g) * 2 + nt) * 4];
                    mma16816(a0, Ah[0], &bh.x); mma16816(a1, Ah[1], &bh.x);
                    mma16816(a0, Ah[0], &bl.x); mma16816(a1, Ah[1], &bl.x);
                    mma16816(a0, Al[0], &bh.x); mma16816(a1, Al[1], &bh.x);
                }
        }
        __syncthreads();   // all warps done reading h/x smem

        // write prefetched x_{t+1} (safe: reads of x_t completed at sync above)
        if (t < SEQ - 1) {
#pragma unroll
            for (int q = 0; q < 4; q++) {
                int i = i4 + q;
                int row = i >> 5, cp = (i & 31) * 2;
                uint32_t off = (uint32_t)row * 144 + (uint32_t)cp * 2;
                *(uint32_t*)(smx + HF_XHI + off) = packh2(px[q].x, px[q].y);
                *(uint32_t*)(smx + HF_XLO + off) = packh2_lo(px[q].x, px[q].y);
            }
        }

        // ---- GRU cell + h store ----
#pragma unroll
        for (int mt = 0; mt < 2; mt++)
#pragma unroll
            for (int nt = 0; nt < 2; nt++) {
                int c0 = w * 16 + nt * 8 + (lane & 3) * 2;
#pragma unroll
                for (int rh = 0; rh < 2; rh++) {
                    int row = mt * 16 + (lane >> 2) + rh * 8;
                    int node = node0 + row;
                    float h2[2];
#pragma unroll
                    for (int j = 0; j < 2; j++) {
                        int d = rh * 2 + j, q = nt * 2 + j;
                        float rv = sigmf(acc[((mt * 4 + 0) * 2 + nt) * 4 + d] + br[q]);
                        float zv = sigmf(acc[((mt * 4 + 1) * 2 + nt) * 4 + d] + bz[q]);
                        float nv = tanhfast(acc[((mt * 4 + 2) * 2 + nt) * 4 + d] + bni[q]
                                  + rv * (acc[((mt * 4 + 3) * 2 + nt) * 4 + d] + bnh[q]));
                        int hx = ((mt * 2 + nt) * 2 + rh) * 2 + j;
                        float hv = (1.f - zv) * nv + zv * hold[hx];
                        hold[hx] = hv;
                        h2[j] = hv;
                    }
                    uint32_t off = (uint32_t)row * 272 + (uint32_t)c0 * 2;
                    *(uint32_t*)(smx + HF_HHI + off) = packh2(h2[0], h2[1]);
                    *(uint32_t*)(smx + HF_HLO + off) = packh2_lo(h2[0], h2[1]);
                    if (t == SEQ - 1 && node < NNODES)
                        *(float2*)&outh[(size_t)node * HID + c0] = make_float2(h2[0], h2[1]);
                }
            }
    }
}

// ============ GAT GEMM via mma: h = x @ W^T, 64 nodes/block ==================
// smem: [0,65536) layer frags (hi|lo) | x_hi @65536 (64x272B) | x_lo @82944 -> 100352 B
#define GG_XHI 65536
#define GG_XLO 82944
#define GG_SMEM 100352

__global__ void __launch_bounds__(256) gat_gemm_kernel(
    const float* __restrict__ Xin, int layer, float* __restrict__ Hout)
{
    extern __shared__ char smx[];
    const int tid = threadIdx.x, w = tid >> 5, lane = tid & 31;
    const int warpM = w >> 2, warpN = w & 3;
    const int node0 = blockIdx.x * 64;

    for (int i = tid; i < 4096; i += 256) ((uint4*)smx)[i] = g_fgat[layer * 4096 + i];
    for (int i = tid; i < 4096; i += 256) {
        int row = i >> 6, cp = (i & 63) * 2;
        int node = node0 + row;
        float2 v = (node < NNODES) ? *(const float2*)&Xin[(size_t)node * HID + cp]
                                   : make_float2(0.f, 0.f);
        uint32_t off = (uint32_t)row * 272 + (uint32_t)cp * 2;
        *(uint32_t*)(smx + GG_XHI + off) = packh2(v.x, v.y);
        *(uint32_t*)(smx + GG_XLO + off) = packh2_lo(v.x, v.y);
    }
    __syncthreads();

    uint32_t sb = smem_u32(smx);
    const int rowl = ((lane >> 3) & 1) * 8 + (lane & 7), khalf = lane >> 4;
    uint32_t ab[2][2];
#pragma unroll
    for (int s = 0; s < 2; s++)
#pragma unroll
        for (int mt = 0; mt < 2; mt++)
            ab[s][mt] = sb + (s ? GG_XLO : GG_XHI)
                      + (uint32_t)(warpM * 32 + mt * 16 + rowl) * 272 + khalf * 16;

    float acc[32];
#pragma unroll
    for (int i = 0; i < 32; i++) acc[i] = 0.f;

#pragma unroll 1
    for (int kt = 0; kt < 8; kt++) {
        uint32_t Ah[2][4], Al[2][4];
        ldsm4(Ah[0], ab[0][0] + kt * 32);
        ldsm4(Ah[1], ab[0][1] + kt * 32);
        ldsm4(Al[0], ab[1][0] + kt * 32);
        ldsm4(Al[1], ab[1][1] + kt * 32);
#pragma unroll
        for (int nt = 0; nt < 4; nt++) {
            int ntg = warpN * 4 + nt;
            const char* fb = smx + ((kt * 16 + ntg) << 8) + (lane << 3);
            uint2 bh = *(const uint2*)fb;
            uint2 bl = *(const uint2*)(fb + 32768);
            float* a0 = &acc[(0 * 4 + nt) * 4];
            float* a1 = &acc[(1 * 4 + nt) * 4];
            mma16816(a0, Ah[0], &bh.x); mma16816(a1, Ah[1], &bh.x);
            mma16816(a0, Ah[0], &bl.x); mma16816(a1, Ah[1], &bl.x);
            mma16816(a0, Al[0], &bh.x); mma16816(a1, Al[1], &bh.x);
        }
    }
#pragma unroll
    for (int mt = 0; mt < 2; mt++)
#pragma unroll
        for (int nt = 0; nt < 4; nt++) {
            int col = warpN * 32 + nt * 8 + (lane & 3) * 2;
#pragma unroll
            for (int rh = 0; rh < 2; rh++) {
                int node = node0 + warpM * 32 + mt * 16 + (lane >> 2) + rh * 8;
                if (node < NNODES) {
                    const float* a = &acc[(mt * 4 + nt) * 4];
                    *(float2*)&Hout[(size_t)node * HID + col] = make_float2(a[rh * 2], a[rh * 2 + 1]);
                }
            }
        }
}

// ---------------- attention prep + edge passes ----------------
__global__ void att_kernel(const float* __restrict__ h1, const float* __restrict__ asrc,
                           const float* __restrict__ adst, int n)
{
    int g = blockIdx.x * blockDim.x + threadIdx.x;
    if (g >= n * NHEAD) return;
    int node = g >> 2, hh = g & 3;
    const float* hp = h1 + (size_t)node * HID + hh * 32;
    float s = 0.f, d = 0.f;
#pragma unroll
    for (int c = 0; c < 32; c += 4) {
        float4 hv = *(const float4*)&hp[c];
        float4 sv = __ldg((const float4*)&asrc[hh * 32 + c]);
        float4 dv = __ldg((const float4*)&adst[hh * 32 + c]);
        s += hv.x * sv.x + hv.y * sv.y + hv.z * sv.z + hv.w * sv.w;
        d += hv.x * dv.x + hv.y * dv.y + hv.z * dv.z + hv.w * dv.w;
    }
    g_as[g] = s; g_ad[g] = d;
    g_den[g] = 0.f;
}

__global__ void zero_kernel(float* p, int n) {
    int i = blockIdx.x * blockDim.x + threadIdx.x;
    if (i < n) p[i] = 0.f;
}

// single pass: e = lrelu(as+ad); ex = exp(e) (no max shift — softmax invariant);
// store ex; accumulate denom
__global__ void edge_expsum_kernel(int E, int n) {
    int tot = E + n;
    for (int i = blockIdx.x * blockDim.x + threadIdx.x; i < tot; i += gridDim.x * blockDim.x) {
        int s, d;
        if (i < E) { s = g_ei[i]; d = g_ei[E + i]; } else { s = d = i - E; }
        float4 a = *(const float4*)&g_as[s * 4];
        float4 b = *(const float4*)&g_ad[d * 4];
        float4 ex = make_float4(__expf(lrelu(a.x + b.x)), __expf(lrelu(a.y + b.y)),
                                __expf(lrelu(a.z + b.z)), __expf(lrelu(a.w + b.w)));
        *(float4*)&g_e[(size_t)i * 4] = ex;
        redAdd4(&g_den[d * 4], ex);
    }
}

__global__ void rden_kernel(int n4) {
    int i = blockIdx.x * blockDim.x + threadIdx.x;
    if (i < n4) g_den[i] = 1.f / (g_den[i] + 1e-16f);
}

__global__ void edge_scatter_kernel(const float* __restrict__ h1, float* __restrict__ out,
                                    int E, int n)
{
    int lane = threadIdx.x & 31;
    int w = (blockIdx.x * blockDim.x + threadIdx.x) >> 5;
    int nwarp = (gridDim.x * blockDim.x) >> 5;
    int tot = E + n;
    for (int i = w; i < tot; i += nwarp) {
        int s, d;
        if (i < E) { s = g_ei[i]; d = g_ei[E + i]; } else { s = d = i - E; }
        float4 ex = *(const float4*)&g_e[(size_t)i * 4];
        float4 rd = *(const float4*)&g_den[d * 4];
        float alpha = f4c(make_float4(ex.x * rd.x, ex.y * rd.y, ex.z * rd.z, ex.w * rd.w),
                          lane >> 3);
        float4 hv = *(const float4*)&h1[(size_t)s * HID + lane * 4];
        redAdd4(&out[(size_t)d * HID + lane * 4],
                make_float4(hv.x * alpha, hv.y * alpha, hv.z * alpha, hv.w * alpha));
    }
}

__global__ void finish_kernel(const float* __restrict__ acc, const float* __restrict__ b,
                              float* __restrict__ xout, int tot)
{
    int i = blockIdx.x * blockDim.x + threadIdx.x;
    if (i < tot) {
        float v = acc[i] + __ldg(&b[i & 127]);
        xout[i] = v > 0.f ? v : expm1f(v);
    }
}

__global__ void clf_kernel(const float* __restrict__ x, const float* __restrict__ wgt,
                           const float* __restrict__ b, float* __restrict__ out, int n)
{
    int lane = threadIdx.x & 31;
    int w = (blockIdx.x * blockDim.x + threadIdx.x) >> 5;
    if (w >= n) return;
    float4 xv = *(const float4*)&x[(size_t)w * HID + lane * 4];
    float4 wv = __ldg((const float4*)&wgt[lane * 4]);
    float s = xv.x * wv.x + xv.y * wv.y + xv.z * wv.z + xv.w * wv.w;
#pragma unroll
    for (int o = 16; o; o >>= 1) s += __shfl_xor_sync(0xffffffffu, s, o);
    if (lane == 0) out[w] = 1.f / (1.f + expf(-(s + __ldg(b))));
}

// ---------------- host side ----------------
static void run_gat(const float* xin, int layer, const float* asrc, const float* adst,
                    const float* b, float* xout, float* h1, float* accb, int E, int n)
{
    gat_gemm_kernel<<<(n + 63) / 64, 256, GG_SMEM>>>(xin, layer, h1);
    att_kernel<<<(n * NHEAD + 255) / 256, 256>>>(h1, asrc, adst, n);
    zero_kernel<<<(n * HID + 255) / 256, 256>>>(accb, n * HID);
    edge_expsum_kernel<<<2048, 256>>>(E, n);
    rden_kernel<<<(n * NHEAD + 255) / 256, 256>>>(n * NHEAD);
    edge_scatter_kernel<<<8192, 256>>>(h1, accb, E, n);
    finish_kernel<<<(n * HID + 255) / 256, 256>>>(accb, b, xout, n * HID);
}

extern "C" void kernel_launch(void* const* d_in, const int* in_sizes, int n_in,
                              void* d_out, int out_size)
{
    (void)in_sizes; (void)n_in; (void)out_size;
    const float* X    = (const float*)d_in[0];
    const void*  EIp  = d_in[1];
    const float* Wih  = (const float*)d_in[2];
    const float* Whh  = (const float*)d_in[3];
    const float* bih  = (const float*)d_in[4];
    const float* bhh  = (const float*)d_in[5];
    const float* g1w  = (const float*)d_in[6];
    const float* g1as = (const float*)d_in[7];
    const float* g1ad = (const float*)d_in[8];
    const float* g1b  = (const float*)d_in[9];
    const float* g2w  = (const float*)d_in[10];
    const float* g2as = (const float*)d_in[11];
    const float* g2ad = (const float*)d_in[12];
    const float* g2b  = (const float*)d_in[13];
    const float* cw   = (const float*)d_in[14];
    const float* cb   = (const float*)d_in[15];
    float* out = (float*)d_out;

    cudaFuncSetAttribute(gru_fused_kernel, cudaFuncAttributeMaxDynamicSharedMemorySize, GF_SMEM);
    cudaFuncSetAttribute(gat_gemm_kernel, cudaFuncAttributeMaxDynamicSharedMemorySize, GG_SMEM);

    float *x0, *x1, *h1, *acc;
    cudaGetSymbolAddress((void**)&x0,  g_x0);
    cudaGetSymbolAddress((void**)&x1,  g_x1);
    cudaGetSymbolAddress((void**)&h1,  g_h1);
    cudaGetSymbolAddress((void**)&acc, g_acc);

    detect_kernel<<<1, 32>>>(EIp);
    convert_kernel<<<2048, 256>>>(EIp, 2 * ECONST);
    fragprep_kernel<<<96, 256>>>(Wih, Whh);
    fragprep_gat_kernel<<<64, 256>>>(g1w, g2w);

    gru_fused_kernel<<<(NNODES + 31) / 32, 256, GF_SMEM>>>(X, bih, bhh, x0);

    run_gat(x0, 0, g1as, g1ad, g1b, x1, h1, acc, ECONST, NNODES);
    run_gat(x1, 1, g2as, g2ad, g2b, x0, h1, acc, ECONST, NNODES);

    clf_kernel<<<(NNODES * 32 + 255) / 256, 256>>>(x0, cw, cb, out, NNODES);
}

// round 13
// speedup vs baseline: 2.5470x; 1.1234x over previous
#include <cuda_runtime.h>
#include <cuda_fp16.h>
#include <cstdint>
#include <cstddef>

#define NNODES 50000
#define SEQ    16
#define FIN    64
#define HID    128
#define G3     384
#define NHEAD  4
#define ECONST 1600000
#define ETOT   (ECONST + NNODES)

// ---------------- scratch (device globals; no runtime allocation) -------------
__device__ float g_x0 [(size_t)NNODES * HID];
__device__ float g_x1 [(size_t)NNODES * HID];
__device__ float g_h1 [(size_t)NNODES * HID];
__device__ float g_acc[(size_t)NNODES * HID];
__device__ float g_as [NNODES * NHEAD];
__device__ float g_ad [NNODES * NHEAD];
__device__ float g_den[NNODES * NHEAD];
__device__ float g_e  [(size_t)ETOT * NHEAD];
__device__ int   g_ei [2 * ECONST];
__device__ int   g_flag[1];
__device__ uint4 g_fih4[6144];    // Wih frags
__device__ uint4 g_fhh4[12288];   // Whh frags
__device__ uint4 g_fgat[8192];    // GAT W frags (2 layers)

// ---------------- helpers ----------------
__device__ __forceinline__ float f4c(const float4 v, int i) {
    switch (i & 3) { case 0: return v.x; case 1: return v.y; case 2: return v.z; default: return v.w; }
}
__device__ __forceinline__ float sigmf(float x) { return 1.f / (1.f + __expf(-x)); }
__device__ __forceinline__ float tanhfast(float x) { return 2.f / (1.f + __expf(-2.f * x)) - 1.f; }
__device__ __forceinline__ float lrelu(float x) { return x >= 0.f ? x : 0.2f * x; }
__device__ __forceinline__ void redAdd4(float* a, float4 v) {
    asm volatile("red.global.add.v4.f32 [%0], {%1,%2,%3,%4};"
                 :: "l"(a), "f"(v.x), "f"(v.y), "f"(v.z), "f"(v.w) : "memory");
}
__device__ __forceinline__ uint32_t smem_u32(const void* p) {
    uint32_t a;
    asm("{ .reg .u64 t; cvta.to.shared.u64 t, %1; cvt.u32.u64 %0, t; }" : "=r"(a) : "l"(p));
    return a;
}
__device__ __forceinline__ uint32_t packh2(float a, float b) {
    __half2 p = __halves2half2(__float2half_rn(a), __float2half_rn(b));
    return *(uint32_t*)&p;
}
__device__ __forceinline__ uint32_t packh2_lo(float a, float b) {
    float ar = a - __half2float(__float2half_rn(a));
    float br = b - __half2float(__float2half_rn(b));
    return packh2(ar, br);
}
__device__ __forceinline__ void mma16816(float* d, const uint32_t* a, const uint32_t* b) {
    asm volatile("mma.sync.aligned.m16n8k16.row.col.f32.f16.f16.f32 "
        "{%0,%1,%2,%3}, {%4,%5,%6,%7}, {%8,%9}, {%0,%1,%2,%3};"
        : "+f"(d[0]), "+f"(d[1]), "+f"(d[2]), "+f"(d[3])
        : "r"(a[0]), "r"(a[1]), "r"(a[2]), "r"(a[3]), "r"(b[0]), "r"(b[1]));
}
__device__ __forceinline__ void ldsm4(uint32_t* r, uint32_t addr) {
    asm volatile("ldmatrix.sync.aligned.m8n8.x4.shared.b16 {%0,%1,%2,%3}, [%4];"
        : "=r"(r[0]), "=r"(r[1]), "=r"(r[2]), "=r"(r[3]) : "r"(addr));
}

// ---------------- edge dtype detect + convert ----------------
__global__ void detect_kernel(const void* p) {
    if (threadIdx.x == 0) {
        const int* q = (const int*)p;
        int all0 = 1;
        for (int i = 1; i < 64; i += 2) if (q[i] != 0) all0 = 0;
        g_flag[0] = all0;
    }
}
__global__ void convert_kernel(const void* p, int tot) {
    int is64 = g_flag[0];
    for (int i = blockIdx.x * blockDim.x + threadIdx.x; i < tot; i += gridDim.x * blockDim.x)
        g_ei[i] = is64 ? (int)((const long long*)p)[i] : ((const int*)p)[i];
}

// ---------------- weight fragment precompute ----------------
__global__ void fragprep_kernel(const float* __restrict__ Wih, const float* __restrict__ Whh) {
    int e = blockIdx.x * blockDim.x + threadIdx.x;
    if (e < 12288) {
        int lane = e & 31, tile = e >> 5;
        int ntg = tile % 48, kt = (tile / 48) & 3, split = tile / 192;
        int n = ntg * 8 + (lane >> 2), k = kt * 16 + (lane & 3) * 2;
        const float* wr = Wih + (size_t)n * FIN;
        float w0 = wr[k], w1 = wr[k + 1], w2 = wr[k + 8], w3 = wr[k + 9];
        uint2 v;
        if (split == 0) { v.x = packh2(w0, w1); v.y = packh2(w2, w3); }
        else            { v.x = packh2_lo(w0, w1); v.y = packh2_lo(w2, w3); }
        ((uint2*)g_fih4)[tile * 32 + lane] = v;
    }
    if (e < 24576) {
        int lane = e & 31, tile = e >> 5;
        int ntg = tile % 48, kt = (tile / 48) & 7, split = tile / 384;
        int n = ntg * 8 + (lane >> 2), k = kt * 16 + (lane & 3) * 2;
        const float* wr = Whh + (size_t)n * HID;
        float w0 = wr[k], w1 = wr[k + 1], w2 = wr[k + 8], w3 = wr[k + 9];
        uint2 v;
        if (split == 0) { v.x = packh2(w0, w1); v.y = packh2(w2, w3); }
        else            { v.x = packh2_lo(w0, w1); v.y = packh2_lo(w2, w3); }
        ((uint2*)g_fhh4)[tile * 32 + lane] = v;
    }
}

__global__ void fragprep_gat_kernel(const float* __restrict__ g1w, const float* __restrict__ g2w) {
    int e = blockIdx.x * blockDim.x + threadIdx.x;
    if (e >= 16384) return;
    int lane = e & 31, tile = e >> 5;
    int layer = tile >> 8, tl = tile & 255;
    int ntg = tl & 15, kt = (tl >> 4) & 7, split = tl >> 7;
    const float* W = layer ? g2w : g1w;
    int n = ntg * 8 + (lane >> 2), k = kt * 16 + (lane & 3) * 2;
    const float* wr = W + (size_t)n * HID;
    float w0 = wr[k], w1 = wr[k + 1], w2 = wr[k + 8], w3 = wr[k + 9];
    uint2 v;
    if (split == 0) { v.x = packh2(w0, w1); v.y = packh2(w2, w3); }
    else            { v.x = packh2_lo(w0, w1); v.y = packh2_lo(w2, w3); }
    ((uint2*)g_fgat)[tile * 32 + lane] = v;
}

// ============ fused GRU: 512 threads (16 warps), 32 nodes/block ===============
// smem: [0,196608) Whh frags (hi|lo) | h_hi @196608 (32x272B) | h_lo @205312
//       | x_hi @214016 (32x144B) | x_lo @218624   -> total 223232 B
#define HF_HHI 196608
#define HF_HLO 205312
#define HF_XHI 214016
#define HF_XLO 218624
#define GF_SMEM 223232

__global__ void __launch_bounds__(512, 1) gru_fused_kernel(
    const float* __restrict__ X, const float* __restrict__ bih,
    const float* __restrict__ bhh, float* __restrict__ outh)
{
    extern __shared__ char smx[];
    const int tid = threadIdx.x, w = tid >> 5, lane = tid & 31;
    const int node0 = blockIdx.x * 32;

    for (int i = tid; i < 12288; i += 512) ((uint4*)smx)[i] = g_fhh4[i];
    {
        uint32_t* hz = (uint32_t*)(smx + HF_HHI);
        for (int i = tid; i < 4352; i += 512) hz[i] = 0;
    }
    // warp w owns output columns [w*8, w*8+8); thread's 2 cols: c = w*8+(lane&3)*2+q
    float br[2], bz[2], bni[2], bnh[2];
#pragma unroll
    for (int q = 0; q < 2; q++) {
        int c = w * 8 + (lane & 3) * 2 + q;
        br[q]  = __ldg(&bih[c]) + __ldg(&bhh[c]);
        bz[q]  = __ldg(&bih[128 + c]) + __ldg(&bhh[128 + c]);
        bni[q] = __ldg(&bih[256 + c]);
        bnh[q] = __ldg(&bhh[256 + c]);
    }

    const int i2 = tid * 2;   // x staging: 2 float2 per thread (1024 total)
    {
#pragma unroll
        for (int q = 0; q < 2; q++) {
            int i = i2 + q;
            int row = i >> 5, cp = (i & 31) * 2;
            int node = node0 + row;
            float2 v = (node < NNODES)
                ? *(const float2*)&X[(size_t)node * (SEQ * FIN) + 0 * FIN + cp]
                : make_float2(0.f, 0.f);
            uint32_t off = (uint32_t)row * 144 + (uint32_t)cp * 2;
            *(uint32_t*)(smx + HF_XHI + off) = packh2(v.x, v.y);
            *(uint32_t*)(smx + HF_XLO + off) = packh2_lo(v.x, v.y);
        }
    }

    uint32_t sb = smem_u32(smx);
    const int rowl = ((lane >> 3) & 1) * 8 + (lane & 7), khalf = lane >> 4;
    uint32_t abh[2][2], abx[2][2];
#pragma unroll
    for (int s = 0; s < 2; s++)
#pragma unroll
        for (int mt = 0; mt < 2; mt++) {
            abh[s][mt] = sb + (s ? HF_HLO : HF_HHI) + (uint32_t)(mt * 16 + rowl) * 272 + khalf * 16;
            abx[s][mt] = sb + (s ? HF_XLO : HF_XHI) + (uint32_t)(mt * 16 + rowl) * 144 + khalf * 16;
        }

    float hold[8];
#pragma unroll
    for (int i = 0; i < 8; i++) hold[i] = 0.f;
    // acc slots: 0=r, 1=z, 2=n_x, 3=n_h ; index (mt*4+g)*4 + d
    float acc[32];

    const uint2* fih = (const uint2*)g_fih4;

    for (int t = 0; t < SEQ; t++) {
        __syncthreads();   // x_t + h(t-1) stores visible

        float2 px[2];
        if (t < SEQ - 1) {
#pragma unroll
            for (int q = 0; q < 2; q++) {
                int i = i2 + q;
                int row = i >> 5, cp = (i & 31) * 2;
                int node = node0 + row;
                px[q] = (node < NNODES)
                    ? *(const float2*)&X[(size_t)node * (SEQ * FIN) + (t + 1) * FIN + cp]
                    : make_float2(0.f, 0.f);
            }
        }

#pragma unroll
        for (int i = 0; i < 32; i++) acc[i] = 0.f;

        // ---- h-side: K=128, Whh frags from smem; warp handles ntg = g*16+w ----
#pragma unroll 1
        for (int kt = 0; kt < 8; kt++) {
            uint32_t Ah[2][4], Al[2][4];
            ldsm4(Ah[0], abh[0][0] + kt * 32);
            ldsm4(Ah[1], abh[0][1] + kt * 32);
            ldsm4(Al[0], abh[1][0] + kt * 32);
            ldsm4(Al[1], abh[1][1] + kt * 32);
#pragma unroll
            for (int g = 0; g < 3; g++) {
                int ntg = g * 16 + w;
                const char* fb = smx + ((kt * 48 + ntg) << 8) + (lane << 3);
                uint2 bh = *(const uint2*)fb;
                uint2 bl = *(const uint2*)(fb + 98304);
                int gs = (g == 2) ? 3 : g;
                float* a0 = &acc[(0 * 4 + gs) * 4];
                float* a1 = &acc[(1 * 4 + gs) * 4];
                mma16816(a0, Ah[0], &bh.x); mma16816(a1, Ah[1], &bh.x);
                mma16816(a0, Ah[0], &bl.x); mma16816(a1, Ah[1], &bl.x);
                mma16816(a0, Al[0], &bh.x); mma16816(a1, Al[1], &bh.x);
            }
        }
        // ---- x-side: K=64, Wih frags from global (L2-resident) ----
#pragma unroll 1
        for (int kt = 0; kt < 4; kt++) {
            uint32_t Ah[2][4], Al[2][4];
            ldsm4(Ah[0], abx[0][0] + kt * 32);
            ldsm4(Ah[1], abx[0][1] + kt * 32);
            ldsm4(Al[0], abx[1][0] + kt * 32);
            ldsm4(Al[1], abx[1][1] + kt * 32);
#pragma unroll
            for (int g = 0; g < 3; g++) {
                int ntg = g * 16 + w;
                uint2 bh = __ldg(&fih[((kt * 48 + ntg) << 5) + lane]);
                uint2 bl = __ldg(&fih[((192 + kt * 48 + ntg) << 5) + lane]);
                float* a0 = &acc[(0 * 4 + g) * 4];
                float* a1 = &acc[(1 * 4 + g) * 4];
                mma16816(a0, Ah[0], &bh.x); mma16816(a1, Ah[1], &bh.x);
                mma16816(a0, Ah[0], &bl.x); mma16816(a1, Ah[1], &bl.x);
                mma16816(a0, Al[0], &bh.x); mma16816(a1, Al[1], &bh.x);
            }
        }
        __syncthreads();   // all warps done reading h/x smem

        if (t < SEQ - 1) {
#pragma unroll
            for (int q = 0; q < 2; q++) {
                int i = i2 + q;
                int row = i >> 5, cp = (i & 31) * 2;
                uint32_t off = (uint32_t)row * 144 + (uint32_t)cp * 2;
                *(uint32_t*)(smx + HF_XHI + off) = packh2(px[q].x, px[q].y);
                *(uint32_t*)(smx + HF_XLO + off) = packh2_lo(px[q].x, px[q].y);
            }
        }

        // ---- GRU cell + h store (8 values/thread) ----
        const int c0 = w * 8 + (lane & 3) * 2;
#pragma unroll
        for (int mt = 0; mt < 2; mt++)
#pragma unroll
            for (int rh = 0; rh < 2; rh++) {
                int row = mt * 16 + (lane >> 2) + rh * 8;
                int node = node0 + row;
                float h2[2];
#pragma unroll
                for (int j = 0; j < 2; j++) {
                    int d = rh * 2 + j;
                    float rv = sigmf(acc[(mt * 4 + 0) * 4 + d] + br[j]);
                    float zv = sigmf(acc[(mt * 4 + 1) * 4 + d] + bz[j]);
                    float nv = tanhfast(acc[(mt * 4 + 2) * 4 + d] + bni[j]
                              + rv * (acc[(mt * 4 + 3) * 4 + d] + bnh[j]));
                    int hx = (mt * 2 + rh) * 2 + j;
                    float hv = (1.f - zv) * nv + zv * hold[hx];
                    hold[hx] = hv;
                    h2[j] = hv;
                }
                uint32_t off = (uint32_t)row * 272 + (uint32_t)c0 * 2;
                *(uint32_t*)(smx + HF_HHI + off) = packh2(h2[0], h2[1]);
                *(uint32_t*)(smx + HF_HLO + off) = packh2_lo(h2[0], h2[1]);
                if (t == SEQ - 1 && node < NNODES)
                    *(float2*)&outh[(size_t)node * HID + c0] = make_float2(h2[0], h2[1]);
            }
    }
}

// ============ GAT GEMM via mma: h = x @ W^T, 64 nodes/block ==================
#define GG_XHI 65536
#define GG_XLO 82944
#define GG_SMEM 100352

__global__ void __launch_bounds__(256) gat_gemm_kernel(
    const float* __restrict__ Xin, int layer, float* __restrict__ Hout)
{
    extern __shared__ char smx[];
    const int tid = threadIdx.x, w = tid >> 5, lane = tid & 31;
    const int warpM = w >> 2, warpN = w & 3;
    const int node0 = blockIdx.x * 64;

    for (int i = tid; i < 4096; i += 256) ((uint4*)smx)[i] = g_fgat[layer * 4096 + i];
    for (int i = tid; i < 4096; i += 256) {
        int row = i >> 6, cp = (i & 63) * 2;
        int node = node0 + row;
        float2 v = (node < NNODES) ? *(const float2*)&Xin[(size_t)node * HID + cp]
                                   : make_float2(0.f, 0.f);
        uint32_t off = (uint32_t)row * 272 + (uint32_t)cp * 2;
        *(uint32_t*)(smx + GG_XHI + off) = packh2(v.x, v.y);
        *(uint32_t*)(smx + GG_XLO + off) = packh2_lo(v.x, v.y);
    }
    __syncthreads();

    uint32_t sb = smem_u32(smx);
    const int rowl = ((lane >> 3) & 1) * 8 + (lane & 7), khalf = lane >> 4;
    uint32_t ab[2][2];
#pragma unroll
    for (int s = 0; s < 2; s++)
#pragma unroll
        for (int mt = 0; mt < 2; mt++)
            ab[s][mt] = sb + (s ? GG_XLO : GG_XHI)
                      + (uint32_t)(warpM * 32 + mt * 16 + rowl) * 272 + khalf * 16;

    float acc[32];
#pragma unroll
    for (int i = 0; i < 32; i++) acc[i] = 0.f;

#pragma unroll 1
    for (int kt = 0; kt < 8; kt++) {
        uint32_t Ah[2][4], Al[2][4];
        ldsm4(Ah[0], ab[0][0] + kt * 32);
        ldsm4(Ah[1], ab[0][1] + kt * 32);
        ldsm4(Al[0], ab[1][0] + kt * 32);
        ldsm4(Al[1], ab[1][1] + kt * 32);
#pragma unroll
        for (int nt = 0; nt < 4; nt++) {
            int ntg = warpN * 4 + nt;
            const char* fb = smx + ((kt * 16 + ntg) << 8) + (lane << 3);
            uint2 bh = *(const uint2*)fb;
            uint2 bl = *(const uint2*)(fb + 32768);
            float* a0 = &acc[(0 * 4 + nt) * 4];
            float* a1 = &acc[(1 * 4 + nt) * 4];
            mma16816(a0, Ah[0], &bh.x); mma16816(a1, Ah[1], &bh.x);
            mma16816(a0, Ah[0], &bl.x); mma16816(a1, Ah[1], &bl.x);
            mma16816(a0, Al[0], &bh.x); mma16816(a1, Al[1], &bh.x);
        }
    }
#pragma unroll
    for (int mt = 0; mt < 2; mt++)
#pragma unroll
        for (int nt = 0; nt < 4; nt++) {
            int col = warpN * 32 + nt * 8 + (lane & 3) * 2;
#pragma unroll
            for (int rh = 0; rh < 2; rh++) {
                int node = node0 + warpM * 32 + mt * 16 + (lane >> 2) + rh * 8;
                if (node < NNODES) {
                    const float* a = &acc[(mt * 4 + nt) * 4];
                    *(float2*)&Hout[(size_t)node * HID + col] = make_float2(a[rh * 2], a[rh * 2 + 1]);
                }
            }
        }
}

// ---------------- attention prep + edge passes ----------------
__global__ void att_kernel(const float* __restrict__ h1, const float* __restrict__ asrc,
                           const float* __restrict__ adst, int n)
{
    int g = blockIdx.x * blockDim.x + threadIdx.x;
    if (g >= n * NHEAD) return;
    int node = g >> 2, hh = g & 3;
    const float* hp = h1 + (size_t)node * HID + hh * 32;
    float s = 0.f, d = 0.f;
#pragma unroll
    for (int c = 0; c < 32; c += 4) {
        float4 hv = *(const float4*)&hp[c];
        float4 sv = __ldg((const float4*)&asrc[hh * 32 + c]);
        float4 dv = __ldg((const float4*)&adst[hh * 32 + c]);
        s += hv.x * sv.x + hv.y * sv.y + hv.z * sv.z + hv.w * sv.w;
        d += hv.x * dv.x + hv.y * dv.y + hv.z * dv.z + hv.w * dv.w;
    }
    g_as[g] = s; g_ad[g] = d;
    g_den[g] = 0.f;
}

__global__ void zero_kernel(float* p, int n) {
    int i = blockIdx.x * blockDim.x + threadIdx.x;
    if (i < n) p[i] = 0.f;
}

__global__ void edge_expsum_kernel(int E, int n) {
    int tot = E + n;
    for (int i = blockIdx.x * blockDim.x + threadIdx.x; i < tot; i += gridDim.x * blockDim.x) {
        int s, d;
        if (i < E) { s = g_ei[i]; d = g_ei[E + i]; } else { s = d = i - E; }
        float4 a = *(const float4*)&g_as[s * 4];
        float4 b = *(const float4*)&g_ad[d * 4];
        float4 ex = make_float4(__expf(lrelu(a.x + b.x)), __expf(lrelu(a.y + b.y)),
                                __expf(lrelu(a.z + b.z)), __expf(lrelu(a.w + b.w)));
        *(float4*)&g_e[(size_t)i * 4] = ex;
        redAdd4(&g_den[d * 4], ex);
    }
}

__global__ void rden_kernel(int n4) {
    int i = blockIdx.x * blockDim.x + threadIdx.x;
    if (i < n4) g_den[i] = 1.f / (g_den[i] + 1e-16f);
}

__global__ void edge_scatter_kernel(const float* __restrict__ h1, float* __restrict__ out,
                                    int E, int n)
{
    int lane = threadIdx.x & 31;
    int w = (blockIdx.x * blockDim.x + threadIdx.x) >> 5;
    int nwarp = (gridDim.x * blockDim.x) >> 5;
    int tot = E + n;
    for (int i = w; i < tot; i += nwarp) {
        int s, d;
        if (i < E) { s = g_ei[i]; d = g_ei[E + i]; } else { s = d = i - E; }
        float4 ex = *(const float4*)&g_e[(size_t)i * 4];
        float4 rd = *(const float4*)&g_den[d * 4];
        float alpha = f4c(make_float4(ex.x * rd.x, ex.y * rd.y, ex.z * rd.z, ex.w * rd.w),
                          lane >> 3);
        float4 hv = *(const float4*)&h1[(size_t)s * HID + lane * 4];
        redAdd4(&out[(size_t)d * HID + lane * 4],
                make_float4(hv.x * alpha, hv.y * alpha, hv.z * alpha, hv.w * alpha));
    }
}

__global__ void finish_kernel(const float* __restrict__ acc, const float* __restrict__ b,
                              float* __restrict__ xout, int tot)
{
    int i = blockIdx.x * blockDim.x + threadIdx.x;
    if (i < tot) {
        float v = acc[i] + __ldg(&b[i & 127]);
        xout[i] = v > 0.f ? v : expm1f(v);
    }
}

__global__ void clf_kernel(const float* __restrict__ x, const float* __restrict__ wgt,
                           const float* __restrict__ b, float* __restrict__ out, int n)
{
    int lane = threadIdx.x & 31;
    int w = (blockIdx.x * blockDim.x + threadIdx.x) >> 5;
    if (w >= n) return;
    float4 xv = *(const float4*)&x[(size_t)w * HID + lane * 4];
    float4 wv = __ldg((const float4*)&wgt[lane * 4]);
    float s = xv.x * wv.x + xv.y * wv.y + xv.z * wv.z + xv.w * wv.w;
#pragma unroll
    for (int o = 16; o; o >>= 1) s += __shfl_xor_sync(0xffffffffu, s, o);
    if (lane == 0) out[w] = 1.f / (1.f + expf(-(s + __ldg(b))));
}

// ---------------- host side ----------------
static void run_gat(const float* xin, int layer, const float* asrc, const float* adst,
                    const float* b, float* xout, float* h1, float* accb, int E, int n)
{
    gat_gemm_kernel<<<(n + 63) / 64, 256, GG_SMEM>>>(xin, layer, h1);
    att_kernel<<<(n * NHEAD + 255) / 256, 256>>>(h1, asrc, adst, n);
    zero_kernel<<<(n * HID + 255) / 256, 256>>>(accb, n * HID);
    edge_expsum_kernel<<<2048, 256>>>(E, n);
    rden_kernel<<<(n * NHEAD + 255) / 256, 256>>>(n * NHEAD);
    edge_scatter_kernel<<<8192, 256>>>(h1, accb, E, n);
    finish_kernel<<<(n * HID + 255) / 256, 256>>>(accb, b, xout, n * HID);
}

extern "C" void kernel_launch(void* const* d_in, const int* in_sizes, int n_in,
                              void* d_out, int out_size)
{
    (void)in_sizes; (void)n_in; (void)out_size;
    const float* X    = (const float*)d_in[0];
    const void*  EIp  = d_in[1];
    const float* Wih  = (const float*)d_in[2];
    const float* Whh  = (const float*)d_in[3];
    const float* bih  = (const float*)d_in[4];
    const float* bhh  = (const float*)d_in[5];
    const float* g1w  = (const float*)d_in[6];
    const float* g1as = (const float*)d_in[7];
    const float* g1ad = (const float*)d_in[8];
    const float* g1b  = (const float*)d_in[9];
    const float* g2w  = (const float*)d_in[10];
    const float* g2as = (const float*)d_in[11];
    const float* g2ad = (const float*)d_in[12];
    const float* g2b  = (const float*)d_in[13];
    const float* cw   = (const float*)d_in[14];
    const float* cb   = (const float*)d_in[15];
    float* out = (float*)d_out;

    cudaFuncSetAttribute(gru_fused_kernel, cudaFuncAttributeMaxDynamicSharedMemorySize, GF_SMEM);
    cudaFuncSetAttribute(gat_gemm_kernel, cudaFuncAttributeMaxDynamicSharedMemorySize, GG_SMEM);

    float *x0, *x1, *h1, *acc;
    cudaGetSymbolAddress((void**)&x0,  g_x0);
    cudaGetSymbolAddress((void**)&x1,  g_x1);
    cudaGetSymbolAddress((void**)&h1,  g_h1);
    cudaGetSymbolAddress((void**)&acc, g_acc);

    detect_kernel<<<1, 32>>>(EIp);
    convert_kernel<<<2048, 256>>>(EIp, 2 * ECONST);
    fragprep_kernel<<<96, 256>>>(Wih, Whh);
    fragprep_gat_kernel<<<64, 256>>>(g1w, g2w);

    gru_fused_kernel<<<(NNODES + 31) / 32, 512, GF_SMEM>>>(X, bih, bhh, x0);

    run_gat(x0, 0, g1as, g1ad, g1b, x1, h1, acc, ECONST, NNODES);
    run_gat(x1, 1, g2as, g2ad, g2b, x0, h1, acc, ECONST, NNODES);

    clf_kernel<<<(NNODES * 32 + 255) / 256, 256>>>(x0, cw, cb, out, NNODES);
}